// round 4
// baseline (speedup 1.0000x reference)
#include <cuda_runtime.h>
#include <cuda_bf16.h>
#include <cstdint>
#include <math.h>

#define BB 2
#define SS 2048
#define DD 1024
#define HH 16
#define DHH 64
#define MTOT (BB*SS)   // 4096

// Scratch (alloc-free rule)
__device__ __align__(256) float g_Qp[BB*SS*DD];
__device__ __align__(256) float g_Kp[BB*SS*DD];
__device__ __align__(256) float g_Vp[BB*SS*DD];
__device__ __align__(256) float g_X [BB*SS*DD];
__device__ __align__(256) __nv_bfloat16 g_Whi[4][DD*DD];  // K-major [n][k]
__device__ __align__(256) __nv_bfloat16 g_Wlo[4][DD*DD];
__device__ __align__(256) __nv_bfloat16 g_Ahi[MTOT*DD];
__device__ __align__(256) __nv_bfloat16 g_Alo[MTOT*DD];

// ============================================================================
// helpers
// ============================================================================
__device__ __forceinline__ uint32_t smem_u32(const void* p) {
    uint32_t a;
    asm("{ .reg .u64 t; cvta.to.shared.u64 t, %1; cvt.u32.u64 %0, t; }"
        : "=r"(a) : "l"(p));
    return a;
}
__device__ __forceinline__ void cp_async16(uint32_t dst, const void* src) {
    asm volatile("cp.async.cg.shared.global [%0], [%1], 16;" :: "r"(dst), "l"(src));
}
#define CP_COMMIT() asm volatile("cp.async.commit_group;" ::: "memory")

#define MMA_BF16(c, a, b) \
    asm volatile("mma.sync.aligned.m16n8k16.row.col.f32.bf16.bf16.f32 " \
        "{%0,%1,%2,%3}, {%4,%5,%6,%7}, {%8,%9}, {%0,%1,%2,%3};" \
        : "+f"((c)[0]), "+f"((c)[1]), "+f"((c)[2]), "+f"((c)[3]) \
        : "r"((a)[0]), "r"((a)[1]), "r"((a)[2]), "r"((a)[3]), \
          "r"((b)[0]), "r"((b)[1]))

// ============================================================================
// Weight transpose + bf16 hi/lo split:  Whi/Wlo[n*K + k] = split(W[k*N + n])
// ============================================================================
__global__ __launch_bounds__(256) void trans_split_kernel(
    const float* __restrict__ in,
    __nv_bfloat16* __restrict__ hi, __nv_bfloat16* __restrict__ lo)
{
    __shared__ float t[32][33];
    int x = blockIdx.x * 32 + threadIdx.x;
    int y = blockIdx.y * 32 + threadIdx.y;
    #pragma unroll
    for (int j = 0; j < 32; j += 8)
        t[threadIdx.y + j][threadIdx.x] = in[(size_t)(y + j) * DD + x];
    __syncthreads();
    int x2 = blockIdx.y * 32 + threadIdx.x;   // k
    int y2 = blockIdx.x * 32 + threadIdx.y;   // n
    #pragma unroll
    for (int j = 0; j < 32; j += 8) {
        float w = t[threadIdx.x][threadIdx.y + j];
        __nv_bfloat16 h = __float2bfloat16_rn(w);
        __nv_bfloat16 l = __float2bfloat16_rn(w - __bfloat162float(h));
        hi[(size_t)(y2 + j) * DD + x2] = h;
        lo[(size_t)(y2 + j) * DD + x2] = l;
    }
}

// ============================================================================
// Activation bf16 hi/lo split (elementwise, vectorized)
// ============================================================================
__global__ __launch_bounds__(256) void split_kernel(
    const float* __restrict__ a,
    __nv_bfloat16* __restrict__ hi, __nv_bfloat16* __restrict__ lo, int n4)
{
    int i = blockIdx.x * blockDim.x + threadIdx.x;
    if (i >= n4) return;
    float4 v = ((const float4*)a)[i];
    __nv_bfloat16 hx = __float2bfloat16_rn(v.x);
    __nv_bfloat16 hy = __float2bfloat16_rn(v.y);
    __nv_bfloat16 hz = __float2bfloat16_rn(v.z);
    __nv_bfloat16 hw = __float2bfloat16_rn(v.w);
    __nv_bfloat162 h0; h0.x = hx; h0.y = hy;
    __nv_bfloat162 h1; h1.x = hz; h1.y = hw;
    __nv_bfloat162 l0, l1;
    l0.x = __float2bfloat16_rn(v.x - __bfloat162float(hx));
    l0.y = __float2bfloat16_rn(v.y - __bfloat162float(hy));
    l1.x = __float2bfloat16_rn(v.z - __bfloat162float(hz));
    l1.y = __float2bfloat16_rn(v.w - __bfloat162float(hw));
    ((__nv_bfloat162*)hi)[i*2+0] = h0;
    ((__nv_bfloat162*)hi)[i*2+1] = h1;
    ((__nv_bfloat162*)lo)[i*2+0] = l0;
    ((__nv_bfloat162*)lo)[i*2+1] = l1;
}

// ============================================================================
// bf16-split tensor-core GEMM:
//   C[M=4096, N=1024] = A[M,K] @ W[N,K]^T + bias,  via 3x mma.sync bf16
//   (hi*hi + hi*lo + lo*hi), fp32 accumulate.
// CTA 128x128, BK=32, cp.async double buffer, 8 warps of 64x32.
// SMEM tiles: row pitch 80B (32 bf16 + 8 pad) -> conflict-free frag loads.
// ============================================================================
#define PITCH   80
#define T_AH    0
#define T_AL    10240
#define T_BH    20480
#define T_BL    30720
#define STAGE   40960
#define GEMM_SMEM (2*STAGE)

__device__ __forceinline__ void load_chunk_g(
    uint32_t sbase, int buf,
    const __nv_bfloat16* __restrict__ Ah, const __nv_bfloat16* __restrict__ Al,
    const __nv_bfloat16* __restrict__ Bh, const __nv_bfloat16* __restrict__ Bl,
    int bm, int bn, int k0, int tid)
{
    uint32_t s = sbase + buf * STAGE;
    #pragma unroll
    for (int it = 0; it < 2; ++it) {
        int idx = tid + it * 256;          // 0..511
        int row = idx >> 2;                // 0..127
        int qq  = idx & 3;                 // 0..3
        uint32_t doff = (uint32_t)(row * PITCH + qq * 16);
        size_t ga = (size_t)(bm + row) * DD + k0 + qq * 8;
        size_t gb = (size_t)(bn + row) * DD + k0 + qq * 8;
        cp_async16(s + T_AH + doff, Ah + ga);
        cp_async16(s + T_AL + doff, Al + ga);
        cp_async16(s + T_BH + doff, Bh + gb);
        cp_async16(s + T_BL + doff, Bl + gb);
    }
    CP_COMMIT();
}

__global__ __launch_bounds__(256, 1) void gemm_split(
    const __nv_bfloat16* __restrict__ Ah, const __nv_bfloat16* __restrict__ Al,
    const __nv_bfloat16* __restrict__ Bh, const __nv_bfloat16* __restrict__ Bl,
    const float* __restrict__ bias, float* __restrict__ C)
{
    extern __shared__ char smem[];
    const uint32_t sbase = smem_u32(smem);
    const int tid  = threadIdx.x;
    const int wid  = tid >> 5;
    const int lane = tid & 31;
    const int warp_m = wid & 1;        // 0..1
    const int warp_n = wid >> 1;       // 0..3
    const int bm = blockIdx.y * 128;
    const int bn = blockIdx.x * 128;

    float c[4][4][4];
    #pragma unroll
    for (int i = 0; i < 4; ++i)
        #pragma unroll
        for (int j = 0; j < 4; ++j)
            #pragma unroll
            for (int e = 0; e < 4; ++e) c[i][j][e] = 0.f;

    // prologue
    load_chunk_g(sbase, 0, Ah, Al, Bh, Bl, bm, bn, 0,  tid);
    load_chunk_g(sbase, 1, Ah, Al, Bh, Bl, bm, bn, 32, tid);

    const int NCHUNK = DD / 32;  // 32
    for (int i = 0; i < NCHUNK; ++i) {
        const int buf = i & 1;
        if (i < NCHUNK - 1) asm volatile("cp.async.wait_group 1;" ::: "memory");
        else                asm volatile("cp.async.wait_group 0;" ::: "memory");
        __syncthreads();

        const char* base = smem + buf * STAGE;
        #pragma unroll
        for (int ks = 0; ks < 2; ++ks) {
            const int kb = ks * 32 + (lane & 3) * 4;   // byte offset in row
            uint32_t ah[4][4], al[4][4], bh[4][2], bl[4][2];
            #pragma unroll
            for (int mf = 0; mf < 4; ++mf) {
                int r = warp_m * 64 + mf * 16 + (lane >> 2);
                const char* pa = base + T_AH + r * PITCH + kb;
                ah[mf][0] = *(const uint32_t*)(pa);
                ah[mf][1] = *(const uint32_t*)(pa + 8 * PITCH);
                ah[mf][2] = *(const uint32_t*)(pa + 16);
                ah[mf][3] = *(const uint32_t*)(pa + 8 * PITCH + 16);
                const char* pl = base + T_AL + r * PITCH + kb;
                al[mf][0] = *(const uint32_t*)(pl);
                al[mf][1] = *(const uint32_t*)(pl + 8 * PITCH);
                al[mf][2] = *(const uint32_t*)(pl + 16);
                al[mf][3] = *(const uint32_t*)(pl + 8 * PITCH + 16);
            }
            #pragma unroll
            for (int nf = 0; nf < 4; ++nf) {
                int r = warp_n * 32 + nf * 8 + (lane >> 2);
                const char* pb = base + T_BH + r * PITCH + kb;
                bh[nf][0] = *(const uint32_t*)(pb);
                bh[nf][1] = *(const uint32_t*)(pb + 16);
                const char* pl = base + T_BL + r * PITCH + kb;
                bl[nf][0] = *(const uint32_t*)(pl);
                bl[nf][1] = *(const uint32_t*)(pl + 16);
            }
            #pragma unroll
            for (int mf = 0; mf < 4; ++mf)
                #pragma unroll
                for (int nf = 0; nf < 4; ++nf) {
                    MMA_BF16(c[mf][nf], ah[mf], bh[nf]);
                    MMA_BF16(c[mf][nf], ah[mf], bl[nf]);
                    MMA_BF16(c[mf][nf], al[mf], bh[nf]);
                }
        }
        __syncthreads();
        if (i + 2 < NCHUNK)
            load_chunk_g(sbase, buf, Ah, Al, Bh, Bl, bm, bn, (i + 2) * 32, tid);
    }

    // epilogue: bias add + fp32 store
    #pragma unroll
    for (int mf = 0; mf < 4; ++mf) {
        int m0 = bm + warp_m * 64 + mf * 16 + (lane >> 2);
        #pragma unroll
        for (int nf = 0; nf < 4; ++nf) {
            int n = bn + warp_n * 32 + nf * 8 + (lane & 3) * 2;
            float2 bb = *(const float2*)&bias[n];
            float2 o0, o1;
            o0.x = c[mf][nf][0] + bb.x;  o0.y = c[mf][nf][1] + bb.y;
            o1.x = c[mf][nf][2] + bb.x;  o1.y = c[mf][nf][3] + bb.y;
            *(float2*)&C[(size_t)m0 * DD + n]       = o0;
            *(float2*)&C[(size_t)(m0 + 8) * DD + n] = o1;
        }
    }
}

// ============================================================================
// Flash attention (fp32 SIMT, online softmax, NO 1/sqrt(dk) scaling)
// Output written with the reference's buggy swapaxes layout:
//   X[((h*B + b)*S + s)*DH + d]
// ============================================================================
#define QS_PITCH 68
#define PS_PITCH 68

__global__ __launch_bounds__(256) void attn_kernel(
    const float* __restrict__ Qp, const float* __restrict__ Kp,
    const float* __restrict__ Vp, float* __restrict__ X)
{
    extern __shared__ float sm[];
    float* Qs  = sm;                        // 64 x 68
    float* Kst = Qs  + 64 * QS_PITCH;       // 64 x 64  [d][key]
    float* Vs  = Kst + 64 * 64;             // 64 x 64  [key][d]
    float* Ps  = Vs  + 64 * 64;             // 64 x 68

    const int tid = threadIdx.x;
    const int tx = tid & 15;
    const int ty = tid >> 4;
    const int q0 = blockIdx.x * 64;
    const int bh = blockIdx.y;
    const int b  = bh >> 4;
    const int h  = bh & 15;

    const float* Qbase = Qp + (size_t)b * SS * DD + h * DHH;
    const float* Kbase = Kp + (size_t)b * SS * DD + h * DHH;
    const float* Vbase = Vp + (size_t)b * SS * DD + h * DHH;

    #pragma unroll
    for (int u = 0; u < 4; ++u) {
        int f  = tid + u * 256;
        int r  = f >> 4;
        int c4 = f & 15;
        float4 q4 = *(const float4*)&Qbase[(size_t)(q0 + r) * DD + c4 * 4];
        *(float4*)&Qs[r * QS_PITCH + c4 * 4] = q4;
    }

    float m_i[4], l_i[4], o[4][4];
    #pragma unroll
    for (int i = 0; i < 4; ++i) {
        m_i[i] = -1e30f; l_i[i] = 0.f;
        #pragma unroll
        for (int j = 0; j < 4; ++j) o[i][j] = 0.f;
    }

    for (int kt = 0; kt < SS / 64; ++kt) {
        #pragma unroll
        for (int u = 0; u < 4; ++u) {
            int f  = tid + u * 256;
            int r  = f >> 4;
            int c4 = f & 15;
            float4 k4 = *(const float4*)&Kbase[(size_t)(kt*64 + r) * DD + c4 * 4];
            Kst[(c4*4+0)*64 + r] = k4.x;
            Kst[(c4*4+1)*64 + r] = k4.y;
            Kst[(c4*4+2)*64 + r] = k4.z;
            Kst[(c4*4+3)*64 + r] = k4.w;
            float4 v4 = *(const float4*)&Vbase[(size_t)(kt*64 + r) * DD + c4 * 4];
            *(float4*)&Vs[r * 64 + c4 * 4] = v4;
        }
        __syncthreads();

        float s[4][4];
        #pragma unroll
        for (int i = 0; i < 4; ++i)
            #pragma unroll
            for (int j = 0; j < 4; ++j) s[i][j] = 0.f;

        #pragma unroll 8
        for (int d = 0; d < 64; ++d) {
            float4 kv = *(const float4*)&Kst[d * 64 + tx * 4];
            #pragma unroll
            for (int i = 0; i < 4; ++i) {
                float qv = Qs[(ty*4 + i) * QS_PITCH + d];
                s[i][0] += qv * kv.x;
                s[i][1] += qv * kv.y;
                s[i][2] += qv * kv.z;
                s[i][3] += qv * kv.w;
            }
        }

        #pragma unroll
        for (int i = 0; i < 4; ++i) {
            float mx = fmaxf(fmaxf(s[i][0], s[i][1]), fmaxf(s[i][2], s[i][3]));
            #pragma unroll
            for (int off = 1; off < 16; off <<= 1)
                mx = fmaxf(mx, __shfl_xor_sync(0xffffffffu, mx, off));
            float m_new = fmaxf(m_i[i], mx);
            float scale = __expf(m_i[i] - m_new);
            float p0 = __expf(s[i][0] - m_new);
            float p1 = __expf(s[i][1] - m_new);
            float p2 = __expf(s[i][2] - m_new);
            float p3 = __expf(s[i][3] - m_new);
            float ps = p0 + p1 + p2 + p3;
            #pragma unroll
            for (int off = 1; off < 16; off <<= 1)
                ps += __shfl_xor_sync(0xffffffffu, ps, off);
            l_i[i] = l_i[i] * scale + ps;
            m_i[i] = m_new;
            #pragma unroll
            for (int j = 0; j < 4; ++j) o[i][j] *= scale;
            float4 p4 = make_float4(p0, p1, p2, p3);
            *(float4*)&Ps[(ty*4 + i) * PS_PITCH + tx * 4] = p4;
        }
        __syncthreads();

        #pragma unroll 8
        for (int k = 0; k < 64; ++k) {
            float4 vv = *(const float4*)&Vs[k * 64 + tx * 4];
            #pragma unroll
            for (int i = 0; i < 4; ++i) {
                float pv = Ps[(ty*4 + i) * PS_PITCH + k];
                o[i][0] += pv * vv.x;
                o[i][1] += pv * vv.y;
                o[i][2] += pv * vv.z;
                o[i][3] += pv * vv.w;
            }
        }
        __syncthreads();
    }

    #pragma unroll
    for (int i = 0; i < 4; ++i) {
        int r = ty*4 + i;
        float inv = 1.0f / l_i[i];
        float4 ov = make_float4(o[i][0]*inv, o[i][1]*inv, o[i][2]*inv, o[i][3]*inv);
        size_t idx = (((size_t)(h * BB + b) * SS) + (q0 + r)) * DHH + tx * 4;
        *(float4*)&X[idx] = ov;
    }
}

#define ATTN_SMEM ((64*QS_PITCH + 64*64 + 64*64 + 64*PS_PITCH) * (int)sizeof(float))

extern "C" void kernel_launch(void* const* d_in, const int* in_sizes, int n_in,
                              void* d_out, int out_size)
{
    const float* q  = (const float*)d_in[0];
    const float* k  = (const float*)d_in[1];
    const float* v  = (const float*)d_in[2];
    const float* wq = (const float*)d_in[3];
    const float* bq = (const float*)d_in[4];
    const float* wk = (const float*)d_in[5];
    const float* bk = (const float*)d_in[6];
    const float* wv = (const float*)d_in[7];
    const float* bv = (const float*)d_in[8];
    const float* wo = (const float*)d_in[9];
    const float* bo = (const float*)d_in[10];
    float* out = (float*)d_out;

    float *Qp, *Kp, *Vp, *X;
    __nv_bfloat16 *Whi, *Wlo, *Ahi, *Alo;
    cudaGetSymbolAddress((void**)&Qp,  g_Qp);
    cudaGetSymbolAddress((void**)&Kp,  g_Kp);
    cudaGetSymbolAddress((void**)&Vp,  g_Vp);
    cudaGetSymbolAddress((void**)&X,   g_X);
    cudaGetSymbolAddress((void**)&Whi, g_Whi);
    cudaGetSymbolAddress((void**)&Wlo, g_Wlo);
    cudaGetSymbolAddress((void**)&Ahi, g_Ahi);
    cudaGetSymbolAddress((void**)&Alo, g_Alo);

    cudaFuncSetAttribute(attn_kernel,
                         cudaFuncAttributeMaxDynamicSharedMemorySize, ATTN_SMEM);
    cudaFuncSetAttribute(gemm_split,
                         cudaFuncAttributeMaxDynamicSharedMemorySize, GEMM_SMEM);

    // Weights: transpose to K-major + bf16 hi/lo split
    dim3 tGrid(DD / 32, DD / 32), tBlk(32, 8);
    trans_split_kernel<<<tGrid, tBlk>>>(wq, Whi + 0*DD*DD, Wlo + 0*DD*DD);
    trans_split_kernel<<<tGrid, tBlk>>>(wk, Whi + 1*DD*DD, Wlo + 1*DD*DD);
    trans_split_kernel<<<tGrid, tBlk>>>(wv, Whi + 2*DD*DD, Wlo + 2*DD*DD);
    trans_split_kernel<<<tGrid, tBlk>>>(wo, Whi + 3*DD*DD, Wlo + 3*DD*DD);

    const int n4 = MTOT * DD / 4;
    dim3 sGrid((n4 + 255) / 256);
    dim3 gGrid(DD / 128, MTOT / 128);   // (8, 32)

    // Q projection
    split_kernel<<<sGrid, 256>>>(q, Ahi, Alo, n4);
    gemm_split<<<gGrid, 256, GEMM_SMEM>>>(Ahi, Alo, Whi + 0*DD*DD, Wlo + 0*DD*DD, bq, Qp);
    // K projection
    split_kernel<<<sGrid, 256>>>(k, Ahi, Alo, n4);
    gemm_split<<<gGrid, 256, GEMM_SMEM>>>(Ahi, Alo, Whi + 1*DD*DD, Wlo + 1*DD*DD, bk, Kp);
    // V projection
    split_kernel<<<sGrid, 256>>>(v, Ahi, Alo, n4);
    gemm_split<<<gGrid, 256, GEMM_SMEM>>>(Ahi, Alo, Whi + 2*DD*DD, Wlo + 2*DD*DD, bv, Vp);

    // Attention (fp32 SIMT)
    dim3 aGrid(SS / 64, BB * HH);       // (32, 32)
    attn_kernel<<<aGrid, 256, ATTN_SMEM>>>(Qp, Kp, Vp, X);

    // Output projection
    split_kernel<<<sGrid, 256>>>(X, Ahi, Alo, n4);
    gemm_split<<<gGrid, 256, GEMM_SMEM>>>(Ahi, Alo, Whi + 3*DD*DD, Wlo + 3*DD*DD, bo, out);
}

// round 5
// speedup vs baseline: 1.8507x; 1.8507x over previous
#include <cuda_runtime.h>
#include <cuda_bf16.h>
#include <cuda_fp16.h>
#include <cstdint>
#include <math.h>

#define BB 2
#define SS 2048
#define DD 1024
#define HH 16
#define DHH 64
#define MTOT (BB*SS)

__device__ __align__(256) __nv_bfloat16 g_Whi[4][DD*DD];
__device__ __align__(256) __nv_bfloat16 g_Wlo[4][DD*DD];
__device__ __align__(256) __nv_bfloat16 g_Ahi[MTOT*DD];
__device__ __align__(256) __nv_bfloat16 g_Alo[MTOT*DD];
__device__ __align__(256) __nv_bfloat16 g_Qhi[MTOT*DD];
__device__ __align__(256) __nv_bfloat16 g_Qlo[MTOT*DD];
__device__ __align__(256) __nv_bfloat16 g_Khi[MTOT*DD];
__device__ __align__(256) __nv_bfloat16 g_Klo[MTOT*DD];
__device__ __align__(256) __half        g_Vh [MTOT*DD];
__device__ __align__(256) __nv_bfloat16 g_Xhi[MTOT*DD];
__device__ __align__(256) __nv_bfloat16 g_Xlo[MTOT*DD];

__device__ __forceinline__ uint32_t smem_u32(const void* p) {
    uint32_t a;
    asm("{ .reg .u64 t; cvta.to.shared.u64 t, %1; cvt.u32.u64 %0, t; }" : "=r"(a) : "l"(p));
    return a;
}
__device__ __forceinline__ void cp_async16(uint32_t dst, const void* src) {
    asm volatile("cp.async.cg.shared.global [%0], [%1], 16;" :: "r"(dst), "l"(src));
}
#define CP_COMMIT() asm volatile("cp.async.commit_group;" ::: "memory")

#define MMA_BF16(c, a, b) \
    asm volatile("mma.sync.aligned.m16n8k16.row.col.f32.bf16.bf16.f32 " \
        "{%0,%1,%2,%3}, {%4,%5,%6,%7}, {%8,%9}, {%0,%1,%2,%3};" \
        : "+f"((c)[0]), "+f"((c)[1]), "+f"((c)[2]), "+f"((c)[3]) \
        : "r"((a)[0]), "r"((a)[1]), "r"((a)[2]), "r"((a)[3]), "r"((b)[0]), "r"((b)[1]))

#define MMA_F16(c, a0, a1, a2, a3, b0, b1) \
    asm volatile("mma.sync.aligned.m16n8k16.row.col.f32.f16.f16.f32 " \
        "{%0,%1,%2,%3}, {%4,%5,%6,%7}, {%8,%9}, {%0,%1,%2,%3};" \
        : "+f"((c)[0]), "+f"((c)[1]), "+f"((c)[2]), "+f"((c)[3]) \
        : "r"(a0), "r"(a1), "r"(a2), "r"(a3), "r"(b0), "r"(b1))

__device__ __forceinline__ uint32_t f2h2(float x, float y) {
    __half2 t = __floats2half2_rn(x, y);
    return *(uint32_t*)&t;
}

// ============ weight transpose + split ============
__global__ __launch_bounds__(256) void trans_split_kernel(
    const float* __restrict__ in, __nv_bfloat16* __restrict__ hi, __nv_bfloat16* __restrict__ lo)
{
    __shared__ float t[32][33];
    int x = blockIdx.x * 32 + threadIdx.x;
    int y = blockIdx.y * 32 + threadIdx.y;
    #pragma unroll
    for (int j = 0; j < 32; j += 8)
        t[threadIdx.y + j][threadIdx.x] = in[(size_t)(y + j) * DD + x];
    __syncthreads();
    int x2 = blockIdx.y * 32 + threadIdx.x;
    int y2 = blockIdx.x * 32 + threadIdx.y;
    #pragma unroll
    for (int j = 0; j < 32; j += 8) {
        float w = t[threadIdx.x][threadIdx.y + j];
        __nv_bfloat16 h = __float2bfloat16_rn(w);
        hi[(size_t)(y2 + j) * DD + x2] = h;
        lo[(size_t)(y2 + j) * DD + x2] = __float2bfloat16_rn(w - __bfloat162float(h));
    }
}

// ============ activation split ============
__global__ __launch_bounds__(256) void split_kernel(
    const float* __restrict__ a, __nv_bfloat16* __restrict__ hi, __nv_bfloat16* __restrict__ lo, int n4)
{
    int i = blockIdx.x * blockDim.x + threadIdx.x;
    if (i >= n4) return;
    float4 v = ((const float4*)a)[i];
    __nv_bfloat16 hx = __float2bfloat16_rn(v.x), hy = __float2bfloat16_rn(v.y);
    __nv_bfloat16 hz = __float2bfloat16_rn(v.z), hw = __float2bfloat16_rn(v.w);
    __nv_bfloat162 h0; h0.x = hx; h0.y = hy;
    __nv_bfloat162 h1; h1.x = hz; h1.y = hw;
    __nv_bfloat162 l0, l1;
    l0.x = __float2bfloat16_rn(v.x - __bfloat162float(hx));
    l0.y = __float2bfloat16_rn(v.y - __bfloat162float(hy));
    l1.x = __float2bfloat16_rn(v.z - __bfloat162float(hz));
    l1.y = __float2bfloat16_rn(v.w - __bfloat162float(hw));
    ((__nv_bfloat162*)hi)[i*2+0] = h0; ((__nv_bfloat162*)hi)[i*2+1] = h1;
    ((__nv_bfloat162*)lo)[i*2+0] = l0; ((__nv_bfloat162*)lo)[i*2+1] = l1;
}

// ============ split-bf16 GEMM, templated epilogue ============
// MODE 0: fp32+bias -> C;  MODE 1: bias -> bf16 hi/lo;  MODE 2: bias -> fp16
#define PITCH   80
#define T_AH    0
#define T_AL    10240
#define T_BH    20480
#define T_BL    30720
#define STAGE   40960
#define GEMM_SMEM (2*STAGE)

__device__ __forceinline__ void load_chunk_g(
    uint32_t sbase, int buf,
    const __nv_bfloat16* __restrict__ Ah, const __nv_bfloat16* __restrict__ Al,
    const __nv_bfloat16* __restrict__ Bh, const __nv_bfloat16* __restrict__ Bl,
    int bm, int bn, int k0, int tid)
{
    uint32_t s = sbase + buf * STAGE;
    #pragma unroll
    for (int it = 0; it < 2; ++it) {
        int idx = tid + it * 256;
        int row = idx >> 2, qq = idx & 3;
        uint32_t doff = (uint32_t)(row * PITCH + qq * 16);
        size_t ga = (size_t)(bm + row) * DD + k0 + qq * 8;
        size_t gb = (size_t)(bn + row) * DD + k0 + qq * 8;
        cp_async16(s + T_AH + doff, Ah + ga);
        cp_async16(s + T_AL + doff, Al + ga);
        cp_async16(s + T_BH + doff, Bh + gb);
        cp_async16(s + T_BL + doff, Bl + gb);
    }
    CP_COMMIT();
}

template<int MODE>
__global__ __launch_bounds__(256, 1) void gemm_split(
    const __nv_bfloat16* __restrict__ Ah, const __nv_bfloat16* __restrict__ Al,
    const __nv_bfloat16* __restrict__ Bh, const __nv_bfloat16* __restrict__ Bl,
    const float* __restrict__ bias, float* __restrict__ C,
    __nv_bfloat16* __restrict__ Ohi, __nv_bfloat16* __restrict__ Olo,
    __half* __restrict__ Ofp16)
{
    extern __shared__ char smem[];
    const uint32_t sbase = smem_u32(smem);
    const int tid = threadIdx.x, wid = tid >> 5, lane = tid & 31;
    const int warp_m = wid & 1, warp_n = wid >> 1;
    const int bm = blockIdx.y * 128, bn = blockIdx.x * 128;

    float c[4][4][4];
    #pragma unroll
    for (int i = 0; i < 4; ++i)
        #pragma unroll
        for (int j = 0; j < 4; ++j)
            #pragma unroll
            for (int e = 0; e < 4; ++e) c[i][j][e] = 0.f;

    load_chunk_g(sbase, 0, Ah, Al, Bh, Bl, bm, bn, 0,  tid);
    load_chunk_g(sbase, 1, Ah, Al, Bh, Bl, bm, bn, 32, tid);

    const int NCHUNK = DD / 32;
    for (int i = 0; i < NCHUNK; ++i) {
        const int buf = i & 1;
        if (i < NCHUNK - 1) asm volatile("cp.async.wait_group 1;" ::: "memory");
        else                asm volatile("cp.async.wait_group 0;" ::: "memory");
        __syncthreads();

        const char* base = smem + buf * STAGE;
        #pragma unroll
        for (int ks = 0; ks < 2; ++ks) {
            const int kb = ks * 32 + (lane & 3) * 4;
            uint32_t ah[4][4], al[4][4], bh[4][2], bl[4][2];
            #pragma unroll
            for (int mf = 0; mf < 4; ++mf) {
                int r = warp_m * 64 + mf * 16 + (lane >> 2);
                const char* pa = base + T_AH + r * PITCH + kb;
                ah[mf][0] = *(const uint32_t*)(pa);
                ah[mf][1] = *(const uint32_t*)(pa + 8 * PITCH);
                ah[mf][2] = *(const uint32_t*)(pa + 16);
                ah[mf][3] = *(const uint32_t*)(pa + 8 * PITCH + 16);
                const char* pl = base + T_AL + r * PITCH + kb;
                al[mf][0] = *(const uint32_t*)(pl);
                al[mf][1] = *(const uint32_t*)(pl + 8 * PITCH);
                al[mf][2] = *(const uint32_t*)(pl + 16);
                al[mf][3] = *(const uint32_t*)(pl + 8 * PITCH + 16);
            }
            #pragma unroll
            for (int nf = 0; nf < 4; ++nf) {
                int r = warp_n * 32 + nf * 8 + (lane >> 2);
                const char* pb = base + T_BH + r * PITCH + kb;
                bh[nf][0] = *(const uint32_t*)(pb);
                bh[nf][1] = *(const uint32_t*)(pb + 16);
                const char* pl = base + T_BL + r * PITCH + kb;
                bl[nf][0] = *(const uint32_t*)(pl);
                bl[nf][1] = *(const uint32_t*)(pl + 16);
            }
            #pragma unroll
            for (int mf = 0; mf < 4; ++mf)
                #pragma unroll
                for (int nf = 0; nf < 4; ++nf) {
                    MMA_BF16(c[mf][nf], ah[mf], bh[nf]);
                    MMA_BF16(c[mf][nf], ah[mf], bl[nf]);
                    MMA_BF16(c[mf][nf], al[mf], bh[nf]);
                }
        }
        __syncthreads();
        if (i + 2 < NCHUNK)
            load_chunk_g(sbase, buf, Ah, Al, Bh, Bl, bm, bn, (i + 2) * 32, tid);
    }

    #pragma unroll
    for (int mf = 0; mf < 4; ++mf) {
        int m0 = bm + warp_m * 64 + mf * 16 + (lane >> 2);
        #pragma unroll
        for (int nf = 0; nf < 4; ++nf) {
            int n = bn + warp_n * 32 + nf * 8 + (lane & 3) * 2;
            float2 bb = *(const float2*)&bias[n];
            float v0 = c[mf][nf][0] + bb.x, v1 = c[mf][nf][1] + bb.y;
            float v2 = c[mf][nf][2] + bb.x, v3 = c[mf][nf][3] + bb.y;
            size_t i0 = (size_t)m0 * DD + n, i1 = (size_t)(m0 + 8) * DD + n;
            if (MODE == 0) {
                *(float2*)&C[i0] = make_float2(v0, v1);
                *(float2*)&C[i1] = make_float2(v2, v3);
            } else if (MODE == 1) {
                __nv_bfloat16 h0 = __float2bfloat16_rn(v0), h1 = __float2bfloat16_rn(v1);
                __nv_bfloat16 h2 = __float2bfloat16_rn(v2), h3 = __float2bfloat16_rn(v3);
                __nv_bfloat162 H0; H0.x = h0; H0.y = h1;
                __nv_bfloat162 H1; H1.x = h2; H1.y = h3;
                __nv_bfloat162 L0, L1;
                L0.x = __float2bfloat16_rn(v0 - __bfloat162float(h0));
                L0.y = __float2bfloat16_rn(v1 - __bfloat162float(h1));
                L1.x = __float2bfloat16_rn(v2 - __bfloat162float(h2));
                L1.y = __float2bfloat16_rn(v3 - __bfloat162float(h3));
                *(__nv_bfloat162*)&Ohi[i0] = H0; *(__nv_bfloat162*)&Ohi[i1] = H1;
                *(__nv_bfloat162*)&Olo[i0] = L0; *(__nv_bfloat162*)&Olo[i1] = L1;
            } else {
                *(__half2*)&Ofp16[i0] = __floats2half2_rn(v0, v1);
                *(__half2*)&Ofp16[i1] = __floats2half2_rn(v2, v3);
            }
        }
    }
}

// ============ tensor-core flash attention ============
// 128 q/CTA, 64-key tiles, 8 warps (16 q-rows each). QK: split-bf16 3xMMA.
// P,V: fp16. Online softmax, NO 1/sqrt(dk). Out: bf16 hi/lo, buggy layout
// X[((h*B+b)*S + s)*64 + d].
#define AP 144
#define S_QH 0
#define S_QL (128*AP)
#define S_KH(st) (2*128*AP + (st)*3*64*AP)
#define S_KL(st) (S_KH(st) + 64*AP)
#define S_V(st)  (S_KH(st) + 2*64*AP)
#define ATTN_SMEM (2*128*AP + 2*3*64*AP)

__device__ __forceinline__ void load_kv(uint32_t sb, int st,
    const char* Khb, const char* Klb, const char* Vhb, int key0, int tid)
{
    uint32_t kh = sb + S_KH(st), kl = sb + S_KL(st), vv = sb + S_V(st);
    #pragma unroll
    for (int p = 0; p < 2; ++p) {
        int id = tid + p * 256;
        int row = id >> 3, c = id & 7;
        size_t go = (size_t)(key0 + row) * (DD * 2) + c * 16;
        uint32_t so = (uint32_t)(row * AP + c * 16);
        cp_async16(kh + so, Khb + go);
        cp_async16(kl + so, Klb + go);
        cp_async16(vv + so, Vhb + go);
    }
    CP_COMMIT();
}

__global__ __launch_bounds__(256, 2) void attn_kernel(
    const __nv_bfloat16* __restrict__ Qh, const __nv_bfloat16* __restrict__ Ql,
    const __nv_bfloat16* __restrict__ Kh, const __nv_bfloat16* __restrict__ Kl,
    const __half* __restrict__ Vv,
    __nv_bfloat16* __restrict__ Xhi, __nv_bfloat16* __restrict__ Xlo)
{
    extern __shared__ char sm[];
    const uint32_t sb = smem_u32(sm);
    const int tid = threadIdx.x, lane = tid & 31, w = tid >> 5;
    const int q0 = blockIdx.x * 128;
    const int b = blockIdx.y >> 4, h = blockIdx.y & 15;
    const int g = lane >> 2, qr = lane & 3;
    const int wrow = w * 16;

    const char* Qhb = (const char*)(Qh + (size_t)b * SS * DD + h * 64);
    const char* Qlb = (const char*)(Ql + (size_t)b * SS * DD + h * 64);
    const char* Khb = (const char*)(Kh + (size_t)b * SS * DD + h * 64);
    const char* Klb = (const char*)(Kl + (size_t)b * SS * DD + h * 64);
    const char* Vhb = (const char*)(Vv + (size_t)b * SS * DD + h * 64);

    #pragma unroll
    for (int p = 0; p < 4; ++p) {
        int id = tid + p * 256;
        int row = id >> 3, c = id & 7;
        size_t go = (size_t)(q0 + row) * (DD * 2) + c * 16;
        uint32_t so = (uint32_t)(row * AP + c * 16);
        cp_async16(sb + S_QH + so, Qhb + go);
        cp_async16(sb + S_QL + so, Qlb + go);
    }
    CP_COMMIT();
    load_kv(sb, 0, Khb, Klb, Vhb, 0, tid);
    load_kv(sb, 1, Khb, Klb, Vhb, 64, tid);

    float m0 = -1e30f, m1 = -1e30f, l0 = 0.f, l1 = 0.f;
    float o[8][4];
    #pragma unroll
    for (int j = 0; j < 8; ++j)
        #pragma unroll
        for (int e = 0; e < 4; ++e) o[j][e] = 0.f;

    const int NK = SS / 64;
    const char* QHp = sm + S_QH;
    const char* QLp = sm + S_QL;

    for (int kt = 0; kt < NK; ++kt) {
        const int st = kt & 1;
        if (kt < NK - 1) asm volatile("cp.async.wait_group 1;" ::: "memory");
        else             asm volatile("cp.async.wait_group 0;" ::: "memory");
        __syncthreads();

        const char* KHp = sm + S_KH(st);
        const char* KLp = sm + S_KL(st);

        // ---- S = Q K^T (split bf16) ----
        float s[8][4];
        #pragma unroll
        for (int j = 0; j < 8; ++j)
            #pragma unroll
            for (int e = 0; e < 4; ++e) s[j][e] = 0.f;

        #pragma unroll
        for (int kc = 0; kc < 4; ++kc) {
            const int kb = kc * 32 + qr * 4;
            uint32_t ah[4], al[4];
            const char* pq = QHp + (wrow + g) * AP + kb;
            ah[0] = *(const uint32_t*)(pq);
            ah[1] = *(const uint32_t*)(pq + 8 * AP);
            ah[2] = *(const uint32_t*)(pq + 16);
            ah[3] = *(const uint32_t*)(pq + 8 * AP + 16);
            const char* pl = QLp + (wrow + g) * AP + kb;
            al[0] = *(const uint32_t*)(pl);
            al[1] = *(const uint32_t*)(pl + 8 * AP);
            al[2] = *(const uint32_t*)(pl + 16);
            al[3] = *(const uint32_t*)(pl + 8 * AP + 16);
            #pragma unroll
            for (int nf = 0; nf < 8; ++nf) {
                uint32_t bh[2], bl[2];
                const char* pk = KHp + (nf * 8 + g) * AP + kb;
                bh[0] = *(const uint32_t*)(pk);
                bh[1] = *(const uint32_t*)(pk + 16);
                const char* pkl = KLp + (nf * 8 + g) * AP + kb;
                bl[0] = *(const uint32_t*)(pkl);
                bl[1] = *(const uint32_t*)(pkl + 16);
                MMA_BF16(s[nf], ah, bh);
                MMA_BF16(s[nf], ah, bl);
                MMA_BF16(s[nf], al, bh);
            }
        }

        // ---- online softmax ----
        float mx0 = -1e30f, mx1 = -1e30f;
        #pragma unroll
        for (int j = 0; j < 8; ++j) {
            mx0 = fmaxf(mx0, fmaxf(s[j][0], s[j][1]));
            mx1 = fmaxf(mx1, fmaxf(s[j][2], s[j][3]));
        }
        mx0 = fmaxf(mx0, __shfl_xor_sync(0xffffffffu, mx0, 1));
        mx0 = fmaxf(mx0, __shfl_xor_sync(0xffffffffu, mx0, 2));
        mx1 = fmaxf(mx1, __shfl_xor_sync(0xffffffffu, mx1, 1));
        mx1 = fmaxf(mx1, __shfl_xor_sync(0xffffffffu, mx1, 2));
        float m0n = fmaxf(m0, mx0), m1n = fmaxf(m1, mx1);
        float sc0 = __expf(m0 - m0n), sc1 = __expf(m1 - m1n);
        float ps0 = 0.f, ps1 = 0.f;
        #pragma unroll
        for (int j = 0; j < 8; ++j) {
            s[j][0] = __expf(s[j][0] - m0n);
            s[j][1] = __expf(s[j][1] - m0n);
            s[j][2] = __expf(s[j][2] - m1n);
            s[j][3] = __expf(s[j][3] - m1n);
            ps0 += s[j][0] + s[j][1];
            ps1 += s[j][2] + s[j][3];
            o[j][0] *= sc0; o[j][1] *= sc0;
            o[j][2] *= sc1; o[j][3] *= sc1;
        }
        ps0 += __shfl_xor_sync(0xffffffffu, ps0, 1);
        ps0 += __shfl_xor_sync(0xffffffffu, ps0, 2);
        ps1 += __shfl_xor_sync(0xffffffffu, ps1, 1);
        ps1 += __shfl_xor_sync(0xffffffffu, ps1, 2);
        l0 = l0 * sc0 + ps0;
        l1 = l1 * sc1 + ps1;
        m0 = m0n; m1 = m1n;

        // ---- O += P V (fp16) ----
        const uint32_t vbase = sb + S_V(st);
        #pragma unroll
        for (int kc = 0; kc < 4; ++kc) {
            const int j0 = 2 * kc, j1 = 2 * kc + 1;
            uint32_t a0 = f2h2(s[j0][0], s[j0][1]);
            uint32_t a1 = f2h2(s[j0][2], s[j0][3]);
            uint32_t a2 = f2h2(s[j1][0], s[j1][1]);
            uint32_t a3 = f2h2(s[j1][2], s[j1][3]);
            #pragma unroll
            for (int nfp = 0; nfp < 4; ++nfp) {
                const int nf = 2 * nfp;
                const int mrow = kc * 16 + ((lane >> 3) & 1) * 8 + (lane & 7);
                const int mcol = (nf + (lane >> 4)) * 16;
                uint32_t addr = vbase + (uint32_t)(mrow * AP + mcol);
                uint32_t r0, r1, r2, r3;
                asm volatile("ldmatrix.sync.aligned.m8n8.x4.trans.shared.b16 {%0,%1,%2,%3}, [%4];"
                    : "=r"(r0), "=r"(r1), "=r"(r2), "=r"(r3) : "r"(addr));
                MMA_F16(o[nf],     a0, a1, a2, a3, r0, r1);
                MMA_F16(o[nf + 1], a0, a1, a2, a3, r2, r3);
            }
        }
        __syncthreads();
        if (kt + 2 < NK)
            load_kv(sb, st, Khb, Klb, Vhb, (kt + 2) * 64, tid);
    }

    // ---- epilogue: normalize, split bf16, buggy layout ----
    float inv0 = 1.0f / l0, inv1 = 1.0f / l1;
    size_t r0g = ((size_t)(h * BB + b) * SS + q0 + wrow + g) * 64;
    size_t r1g = r0g + 8 * 64;
    #pragma unroll
    for (int nf = 0; nf < 8; ++nf) {
        int col = nf * 8 + qr * 2;
        float v0 = o[nf][0] * inv0, v1 = o[nf][1] * inv0;
        float v2 = o[nf][2] * inv1, v3 = o[nf][3] * inv1;
        __nv_bfloat16 h0 = __float2bfloat16_rn(v0), h1 = __float2bfloat16_rn(v1);
        __nv_bfloat16 h2 = __float2bfloat16_rn(v2), h3 = __float2bfloat16_rn(v3);
        __nv_bfloat162 H0; H0.x = h0; H0.y = h1;
        __nv_bfloat162 H1; H1.x = h2; H1.y = h3;
        __nv_bfloat162 L0, L1;
        L0.x = __float2bfloat16_rn(v0 - __bfloat162float(h0));
        L0.y = __float2bfloat16_rn(v1 - __bfloat162float(h1));
        L1.x = __float2bfloat16_rn(v2 - __bfloat162float(h2));
        L1.y = __float2bfloat16_rn(v3 - __bfloat162float(h3));
        *(__nv_bfloat162*)&Xhi[r0g + col] = H0;
        *(__nv_bfloat162*)&Xhi[r1g + col] = H1;
        *(__nv_bfloat162*)&Xlo[r0g + col] = L0;
        *(__nv_bfloat162*)&Xlo[r1g + col] = L1;
    }
}

extern "C" void kernel_launch(void* const* d_in, const int* in_sizes, int n_in,
                              void* d_out, int out_size)
{
    const float* q  = (const float*)d_in[0];
    const float* k  = (const float*)d_in[1];
    const float* v  = (const float*)d_in[2];
    const float* wq = (const float*)d_in[3];
    const float* bq = (const float*)d_in[4];
    const float* wk = (const float*)d_in[5];
    const float* bk = (const float*)d_in[6];
    const float* wv = (const float*)d_in[7];
    const float* bv = (const float*)d_in[8];
    const float* wo = (const float*)d_in[9];
    const float* bo = (const float*)d_in[10];
    float* out = (float*)d_out;

    __nv_bfloat16 *Whi, *Wlo, *Ahi, *Alo, *Qhi, *Qlo, *Khi, *Klo, *Xhi, *Xlo;
    __half *Vh;
    cudaGetSymbolAddress((void**)&Whi, g_Whi);
    cudaGetSymbolAddress((void**)&Wlo, g_Wlo);
    cudaGetSymbolAddress((void**)&Ahi, g_Ahi);
    cudaGetSymbolAddress((void**)&Alo, g_Alo);
    cudaGetSymbolAddress((void**)&Qhi, g_Qhi);
    cudaGetSymbolAddress((void**)&Qlo, g_Qlo);
    cudaGetSymbolAddress((void**)&Khi, g_Khi);
    cudaGetSymbolAddress((void**)&Klo, g_Klo);
    cudaGetSymbolAddress((void**)&Xhi, g_Xhi);
    cudaGetSymbolAddress((void**)&Xlo, g_Xlo);
    cudaGetSymbolAddress((void**)&Vh,  g_Vh);

    cudaFuncSetAttribute(gemm_split<0>, cudaFuncAttributeMaxDynamicSharedMemorySize, GEMM_SMEM);
    cudaFuncSetAttribute(gemm_split<1>, cudaFuncAttributeMaxDynamicSharedMemorySize, GEMM_SMEM);
    cudaFuncSetAttribute(gemm_split<2>, cudaFuncAttributeMaxDynamicSharedMemorySize, GEMM_SMEM);
    cudaFuncSetAttribute(attn_kernel,   cudaFuncAttributeMaxDynamicSharedMemorySize, ATTN_SMEM);

    dim3 tGrid(DD / 32, DD / 32), tBlk(32, 8);
    trans_split_kernel<<<tGrid, tBlk>>>(wq, Whi + 0*DD*DD, Wlo + 0*DD*DD);
    trans_split_kernel<<<tGrid, tBlk>>>(wk, Whi + 1*DD*DD, Wlo + 1*DD*DD);
    trans_split_kernel<<<tGrid, tBlk>>>(wv, Whi + 2*DD*DD, Wlo + 2*DD*DD);
    trans_split_kernel<<<tGrid, tBlk>>>(wo, Whi + 3*DD*DD, Wlo + 3*DD*DD);

    const int n4 = MTOT * DD / 4;
    dim3 sGrid((n4 + 255) / 256);
    dim3 gGrid(DD / 128, MTOT / 128);

    split_kernel<<<sGrid, 256>>>(q, Ahi, Alo, n4);
    gemm_split<1><<<gGrid, 256, GEMM_SMEM>>>(Ahi, Alo, Whi + 0*DD*DD, Wlo + 0*DD*DD,
                                             bq, nullptr, Qhi, Qlo, nullptr);
    split_kernel<<<sGrid, 256>>>(k, Ahi, Alo, n4);
    gemm_split<1><<<gGrid, 256, GEMM_SMEM>>>(Ahi, Alo, Whi + 1*DD*DD, Wlo + 1*DD*DD,
                                             bk, nullptr, Khi, Klo, nullptr);
    split_kernel<<<sGrid, 256>>>(v, Ahi, Alo, n4);
    gemm_split<2><<<gGrid, 256, GEMM_SMEM>>>(Ahi, Alo, Whi + 2*DD*DD, Wlo + 2*DD*DD,
                                             bv, nullptr, nullptr, nullptr, Vh);

    dim3 aGrid(SS / 128, BB * HH);   // (16, 32)
    attn_kernel<<<aGrid, 256, ATTN_SMEM>>>(Qhi, Qlo, Khi, Klo, Vh, Xhi, Xlo);

    gemm_split<0><<<gGrid, 256, GEMM_SMEM>>>(Xhi, Xlo, Whi + 3*DD*DD, Wlo + 3*DD*DD,
                                             bo, out, nullptr, nullptr, nullptr);
}

// round 6
// speedup vs baseline: 2.4367x; 1.3166x over previous
#include <cuda_runtime.h>
#include <cuda_bf16.h>
#include <cuda_fp16.h>
#include <cstdint>
#include <math.h>

#define BB 2
#define SS 2048
#define DD 1024
#define HH 16
#define DHH 64
#define MTOT (BB*SS)

__device__ __align__(256) __nv_bfloat16 g_Whi[4][DD*DD];
__device__ __align__(256) __nv_bfloat16 g_Wlo[4][DD*DD];
__device__ __align__(256) __nv_bfloat16 g_Ahi[MTOT*DD];
__device__ __align__(256) __nv_bfloat16 g_Alo[MTOT*DD];
__device__ __align__(256) __nv_bfloat16 g_Qhi[MTOT*DD];
__device__ __align__(256) __nv_bfloat16 g_Qlo[MTOT*DD];
__device__ __align__(256) __nv_bfloat16 g_Khi[MTOT*DD];
__device__ __align__(256) __nv_bfloat16 g_Klo[MTOT*DD];
__device__ __align__(256) __half        g_Vh [MTOT*DD];
__device__ __align__(256) __nv_bfloat16 g_Xhi[MTOT*DD];
__device__ __align__(256) __nv_bfloat16 g_Xlo[MTOT*DD];

__device__ __forceinline__ uint32_t smem_u32(const void* p) {
    uint32_t a;
    asm("{ .reg .u64 t; cvta.to.shared.u64 t, %1; cvt.u32.u64 %0, t; }" : "=r"(a) : "l"(p));
    return a;
}
__device__ __forceinline__ void cp_async16(uint32_t dst, const void* src) {
    asm volatile("cp.async.cg.shared.global [%0], [%1], 16;" :: "r"(dst), "l"(src));
}
#define CP_COMMIT() asm volatile("cp.async.commit_group;" ::: "memory")

#define MMA_BF16(c, a, b0, b1) \
    asm volatile("mma.sync.aligned.m16n8k16.row.col.f32.bf16.bf16.f32 " \
        "{%0,%1,%2,%3}, {%4,%5,%6,%7}, {%8,%9}, {%0,%1,%2,%3};" \
        : "+f"((c)[0]), "+f"((c)[1]), "+f"((c)[2]), "+f"((c)[3]) \
        : "r"((a)[0]), "r"((a)[1]), "r"((a)[2]), "r"((a)[3]), "r"(b0), "r"(b1))

#define MMA_F16(c, a0, a1, a2, a3, b0, b1) \
    asm volatile("mma.sync.aligned.m16n8k16.row.col.f32.f16.f16.f32 " \
        "{%0,%1,%2,%3}, {%4,%5,%6,%7}, {%8,%9}, {%0,%1,%2,%3};" \
        : "+f"((c)[0]), "+f"((c)[1]), "+f"((c)[2]), "+f"((c)[3]) \
        : "r"(a0), "r"(a1), "r"(a2), "r"(a3), "r"(b0), "r"(b1))

#define LDM_X4(r, a) \
    asm volatile("ldmatrix.sync.aligned.m8n8.x4.shared.b16 {%0,%1,%2,%3}, [%4];" \
        : "=r"((r)[0]), "=r"((r)[1]), "=r"((r)[2]), "=r"((r)[3]) : "r"(a))

__device__ __forceinline__ uint32_t f2h2(float x, float y) {
    __half2 t = __floats2half2_rn(x, y);
    return *(uint32_t*)&t;
}

// ============ weight transpose + split ============
__global__ __launch_bounds__(256) void trans_split_kernel(
    const float* __restrict__ in, __nv_bfloat16* __restrict__ hi, __nv_bfloat16* __restrict__ lo)
{
    __shared__ float t[32][33];
    int x = blockIdx.x * 32 + threadIdx.x;
    int y = blockIdx.y * 32 + threadIdx.y;
    #pragma unroll
    for (int j = 0; j < 32; j += 8)
        t[threadIdx.y + j][threadIdx.x] = in[(size_t)(y + j) * DD + x];
    __syncthreads();
    int x2 = blockIdx.y * 32 + threadIdx.x;
    int y2 = blockIdx.x * 32 + threadIdx.y;
    #pragma unroll
    for (int j = 0; j < 32; j += 8) {
        float w = t[threadIdx.x][threadIdx.y + j];
        __nv_bfloat16 h = __float2bfloat16_rn(w);
        hi[(size_t)(y2 + j) * DD + x2] = h;
        lo[(size_t)(y2 + j) * DD + x2] = __float2bfloat16_rn(w - __bfloat162float(h));
    }
}

// ============ activation split ============
__global__ __launch_bounds__(256) void split_kernel(
    const float* __restrict__ a, __nv_bfloat16* __restrict__ hi, __nv_bfloat16* __restrict__ lo, int n4)
{
    int i = blockIdx.x * blockDim.x + threadIdx.x;
    if (i >= n4) return;
    float4 v = ((const float4*)a)[i];
    __nv_bfloat16 hx = __float2bfloat16_rn(v.x), hy = __float2bfloat16_rn(v.y);
    __nv_bfloat16 hz = __float2bfloat16_rn(v.z), hw = __float2bfloat16_rn(v.w);
    __nv_bfloat162 h0; h0.x = hx; h0.y = hy;
    __nv_bfloat162 h1; h1.x = hz; h1.y = hw;
    __nv_bfloat162 l0, l1;
    l0.x = __float2bfloat16_rn(v.x - __bfloat162float(hx));
    l0.y = __float2bfloat16_rn(v.y - __bfloat162float(hy));
    l1.x = __float2bfloat16_rn(v.z - __bfloat162float(hz));
    l1.y = __float2bfloat16_rn(v.w - __bfloat162float(hw));
    ((__nv_bfloat162*)hi)[i*2+0] = h0; ((__nv_bfloat162*)hi)[i*2+1] = h1;
    ((__nv_bfloat162*)lo)[i*2+0] = l0; ((__nv_bfloat162*)lo)[i*2+1] = l1;
}

// ============ split-bf16 GEMM, 3-stage, ldmatrix ============
#define PITCH   80
#define T_AH    0
#define T_AL    10240
#define T_BH    20480
#define T_BL    30720
#define STAGE   40960
#define GEMM_SMEM (3*STAGE)

__device__ __forceinline__ void load_chunk_g(
    uint32_t sbase, int st,
    const __nv_bfloat16* __restrict__ Ah, const __nv_bfloat16* __restrict__ Al,
    const __nv_bfloat16* __restrict__ Bh, const __nv_bfloat16* __restrict__ Bl,
    int bm, int bn, int k0, int tid)
{
    uint32_t s = sbase + st * STAGE;
    #pragma unroll
    for (int it = 0; it < 2; ++it) {
        int idx = tid + it * 256;
        int row = idx >> 2, qq = idx & 3;
        uint32_t doff = (uint32_t)(row * PITCH + qq * 16);
        size_t ga = (size_t)(bm + row) * DD + k0 + qq * 8;
        size_t gb = (size_t)(bn + row) * DD + k0 + qq * 8;
        cp_async16(s + T_AH + doff, Ah + ga);
        cp_async16(s + T_AL + doff, Al + ga);
        cp_async16(s + T_BH + doff, Bh + gb);
        cp_async16(s + T_BL + doff, Bl + gb);
    }
    CP_COMMIT();
}

// MODE 0: fp32+bias; MODE 1: bf16 hi/lo; MODE 2: fp16
template<int MODE>
__global__ __launch_bounds__(256, 1) void gemm_split(
    const __nv_bfloat16* __restrict__ Ah, const __nv_bfloat16* __restrict__ Al,
    const __nv_bfloat16* __restrict__ Bh, const __nv_bfloat16* __restrict__ Bl,
    const float* __restrict__ bias, float* __restrict__ C,
    __nv_bfloat16* __restrict__ Ohi, __nv_bfloat16* __restrict__ Olo,
    __half* __restrict__ Ofp16)
{
    extern __shared__ char smem[];
    const uint32_t sbase = smem_u32(smem);
    const int tid = threadIdx.x, wid = tid >> 5, lane = tid & 31;
    const int warp_m = wid & 1, warp_n = wid >> 1;
    const int bm = blockIdx.y * 128, bn = blockIdx.x * 128;

    // ldmatrix per-lane offsets
    const uint32_t a_off = (uint32_t)((warp_m * 64 + (lane & 15)) * PITCH + ((lane >> 4) << 4));
    const uint32_t b_off = (uint32_t)((warp_n * 32 + ((lane >> 4) << 3) + (lane & 7)) * PITCH
                                      + (((lane >> 3) & 1) << 4));

    float c[4][4][4];
    #pragma unroll
    for (int i = 0; i < 4; ++i)
        #pragma unroll
        for (int j = 0; j < 4; ++j)
            #pragma unroll
            for (int e = 0; e < 4; ++e) c[i][j][e] = 0.f;

    load_chunk_g(sbase, 0, Ah, Al, Bh, Bl, bm, bn, 0,  tid);
    load_chunk_g(sbase, 1, Ah, Al, Bh, Bl, bm, bn, 32, tid);

    const int NCHUNK = DD / 32;
    for (int i = 0; i < NCHUNK; ++i) {
        const int st = i % 3;
        if (i < NCHUNK - 1) asm volatile("cp.async.wait_group 1;" ::: "memory");
        else                asm volatile("cp.async.wait_group 0;" ::: "memory");
        __syncthreads();
        if (i + 2 < NCHUNK)
            load_chunk_g(sbase, (i + 2) % 3, Ah, Al, Bh, Bl, bm, bn, (i + 2) * 32, tid);

        const uint32_t stb = sbase + st * STAGE;
        #pragma unroll
        for (int ks = 0; ks < 2; ++ks) {
            const uint32_t kb = ks * 32;
            uint32_t ah[4][4], al[4][4], bh[2][4], bl[2][4];
            #pragma unroll
            for (int mf = 0; mf < 4; ++mf) {
                uint32_t ra = stb + T_AH + a_off + mf * (16 * PITCH) + kb;
                LDM_X4(ah[mf], ra);
                LDM_X4(al[mf], ra + (T_AL - T_AH));
            }
            #pragma unroll
            for (int p = 0; p < 2; ++p) {
                uint32_t rb = stb + T_BH + b_off + p * (16 * PITCH) + kb;
                LDM_X4(bh[p], rb);
                LDM_X4(bl[p], rb + (T_BL - T_BH));
            }
            #pragma unroll
            for (int mf = 0; mf < 4; ++mf)
                #pragma unroll
                for (int nf = 0; nf < 4; ++nf) {
                    const int p = nf >> 1, hh = (nf & 1) * 2;
                    MMA_BF16(c[mf][nf], ah[mf], bh[p][hh], bh[p][hh+1]);
                    MMA_BF16(c[mf][nf], ah[mf], bl[p][hh], bl[p][hh+1]);
                    MMA_BF16(c[mf][nf], al[mf], bh[p][hh], bh[p][hh+1]);
                }
        }
    }

    #pragma unroll
    for (int mf = 0; mf < 4; ++mf) {
        int m0 = bm + warp_m * 64 + mf * 16 + (lane >> 2);
        #pragma unroll
        for (int nf = 0; nf < 4; ++nf) {
            int n = bn + warp_n * 32 + nf * 8 + (lane & 3) * 2;
            float2 bb = *(const float2*)&bias[n];
            float v0 = c[mf][nf][0] + bb.x, v1 = c[mf][nf][1] + bb.y;
            float v2 = c[mf][nf][2] + bb.x, v3 = c[mf][nf][3] + bb.y;
            size_t i0 = (size_t)m0 * DD + n, i1 = (size_t)(m0 + 8) * DD + n;
            if (MODE == 0) {
                *(float2*)&C[i0] = make_float2(v0, v1);
                *(float2*)&C[i1] = make_float2(v2, v3);
            } else if (MODE == 1) {
                __nv_bfloat16 h0 = __float2bfloat16_rn(v0), h1 = __float2bfloat16_rn(v1);
                __nv_bfloat16 h2 = __float2bfloat16_rn(v2), h3 = __float2bfloat16_rn(v3);
                __nv_bfloat162 H0; H0.x = h0; H0.y = h1;
                __nv_bfloat162 H1; H1.x = h2; H1.y = h3;
                __nv_bfloat162 L0, L1;
                L0.x = __float2bfloat16_rn(v0 - __bfloat162float(h0));
                L0.y = __float2bfloat16_rn(v1 - __bfloat162float(h1));
                L1.x = __float2bfloat16_rn(v2 - __bfloat162float(h2));
                L1.y = __float2bfloat16_rn(v3 - __bfloat162float(h3));
                *(__nv_bfloat162*)&Ohi[i0] = H0; *(__nv_bfloat162*)&Ohi[i1] = H1;
                *(__nv_bfloat162*)&Olo[i0] = L0; *(__nv_bfloat162*)&Olo[i1] = L1;
            } else {
                *(__half2*)&Ofp16[i0] = __floats2half2_rn(v0, v1);
                *(__half2*)&Ofp16[i1] = __floats2half2_rn(v2, v3);
            }
        }
    }
}

// ============ tensor-core flash attention (Q frags hoisted, ldmatrix K) ============
#define AP 144
#define S_QH 0
#define S_QL (128*AP)
#define S_KH(st) (2*128*AP + (st)*3*64*AP)
#define S_KL(st) (S_KH(st) + 64*AP)
#define S_V(st)  (S_KH(st) + 2*64*AP)
#define ATTN_SMEM (2*128*AP + 2*3*64*AP)

__device__ __forceinline__ void load_kv(uint32_t sb, int st,
    const char* Khb, const char* Klb, const char* Vhb, int key0, int tid)
{
    uint32_t kh = sb + S_KH(st), kl = sb + S_KL(st), vv = sb + S_V(st);
    #pragma unroll
    for (int p = 0; p < 2; ++p) {
        int id = tid + p * 256;
        int row = id >> 3, c = id & 7;
        size_t go = (size_t)(key0 + row) * (DD * 2) + c * 16;
        uint32_t so = (uint32_t)(row * AP + c * 16);
        cp_async16(kh + so, Khb + go);
        cp_async16(kl + so, Klb + go);
        cp_async16(vv + so, Vhb + go);
    }
    CP_COMMIT();
}

__global__ __launch_bounds__(256, 2) void attn_kernel(
    const __nv_bfloat16* __restrict__ Qh, const __nv_bfloat16* __restrict__ Ql,
    const __nv_bfloat16* __restrict__ Kh, const __nv_bfloat16* __restrict__ Kl,
    const __half* __restrict__ Vv,
    __nv_bfloat16* __restrict__ Xhi, __nv_bfloat16* __restrict__ Xlo)
{
    extern __shared__ char sm[];
    const uint32_t sb = smem_u32(sm);
    const int tid = threadIdx.x, lane = tid & 31, w = tid >> 5;
    const int q0 = blockIdx.x * 128;
    const int b = blockIdx.y >> 4, h = blockIdx.y & 15;
    const int g = lane >> 2, qr = lane & 3;
    const int wrow = w * 16;

    const char* Qhb = (const char*)(Qh + (size_t)b * SS * DD + h * 64);
    const char* Qlb = (const char*)(Ql + (size_t)b * SS * DD + h * 64);
    const char* Khb = (const char*)(Kh + (size_t)b * SS * DD + h * 64);
    const char* Klb = (const char*)(Kl + (size_t)b * SS * DD + h * 64);
    const char* Vhb = (const char*)(Vv + (size_t)b * SS * DD + h * 64);

    #pragma unroll
    for (int p = 0; p < 4; ++p) {
        int id = tid + p * 256;
        int row = id >> 3, c = id & 7;
        size_t go = (size_t)(q0 + row) * (DD * 2) + c * 16;
        uint32_t so = (uint32_t)(row * AP + c * 16);
        cp_async16(sb + S_QH + so, Qhb + go);
        cp_async16(sb + S_QL + so, Qlb + go);
    }
    CP_COMMIT();
    load_kv(sb, 0, Khb, Klb, Vhb, 0, tid);
    load_kv(sb, 1, Khb, Klb, Vhb, 64, tid);

    // hoist Q fragments into registers (reused over all 32 k-tiles)
    asm volatile("cp.async.wait_group 2;" ::: "memory");
    __syncthreads();
    const uint32_t q_off = (uint32_t)((wrow + (lane & 15)) * AP + ((lane >> 4) << 4));
    uint32_t qh[4][4], ql[4][4];
    #pragma unroll
    for (int kc = 0; kc < 4; ++kc) {
        uint32_t ra = sb + S_QH + q_off + kc * 32;
        LDM_X4(qh[kc], ra);
        LDM_X4(ql[kc], ra + (S_QL - S_QH));
    }

    const uint32_t k_off = (uint32_t)((((lane >> 4) << 3) + (lane & 7)) * AP
                                      + (((lane >> 3) & 1) << 4));

    float m0 = -1e30f, m1 = -1e30f, l0 = 0.f, l1 = 0.f;
    float o[8][4];
    #pragma unroll
    for (int j = 0; j < 8; ++j)
        #pragma unroll
        for (int e = 0; e < 4; ++e) o[j][e] = 0.f;

    const int NK = SS / 64;
    for (int kt = 0; kt < NK; ++kt) {
        const int st = kt & 1;
        if (kt < NK - 1) asm volatile("cp.async.wait_group 1;" ::: "memory");
        else             asm volatile("cp.async.wait_group 0;" ::: "memory");
        __syncthreads();

        const uint32_t KHb = sb + S_KH(st);

        // ---- S = Q K^T (split bf16) ----
        float s[8][4];
        #pragma unroll
        for (int j = 0; j < 8; ++j)
            #pragma unroll
            for (int e = 0; e < 4; ++e) s[j][e] = 0.f;

        #pragma unroll
        for (int kc = 0; kc < 4; ++kc) {
            #pragma unroll
            for (int p = 0; p < 4; ++p) {   // nf pairs: nf = 2p, 2p+1
                uint32_t rb = KHb + k_off + p * (16 * AP) + kc * 32;
                uint32_t kh4[4], kl4[4];
                LDM_X4(kh4, rb);
                LDM_X4(kl4, rb + 64 * AP);
                MMA_BF16(s[2*p],   qh[kc], kh4[0], kh4[1]);
                MMA_BF16(s[2*p],   qh[kc], kl4[0], kl4[1]);
                MMA_BF16(s[2*p],   ql[kc], kh4[0], kh4[1]);
                MMA_BF16(s[2*p+1], qh[kc], kh4[2], kh4[3]);
                MMA_BF16(s[2*p+1], qh[kc], kl4[2], kl4[3]);
                MMA_BF16(s[2*p+1], ql[kc], kh4[2], kh4[3]);
            }
        }

        // ---- online softmax ----
        float mx0 = -1e30f, mx1 = -1e30f;
        #pragma unroll
        for (int j = 0; j < 8; ++j) {
            mx0 = fmaxf(mx0, fmaxf(s[j][0], s[j][1]));
            mx1 = fmaxf(mx1, fmaxf(s[j][2], s[j][3]));
        }
        mx0 = fmaxf(mx0, __shfl_xor_sync(0xffffffffu, mx0, 1));
        mx0 = fmaxf(mx0, __shfl_xor_sync(0xffffffffu, mx0, 2));
        mx1 = fmaxf(mx1, __shfl_xor_sync(0xffffffffu, mx1, 1));
        mx1 = fmaxf(mx1, __shfl_xor_sync(0xffffffffu, mx1, 2));
        float m0n = fmaxf(m0, mx0), m1n = fmaxf(m1, mx1);
        float sc0 = __expf(m0 - m0n), sc1 = __expf(m1 - m1n);
        float ps0 = 0.f, ps1 = 0.f;
        #pragma unroll
        for (int j = 0; j < 8; ++j) {
            s[j][0] = __expf(s[j][0] - m0n);
            s[j][1] = __expf(s[j][1] - m0n);
            s[j][2] = __expf(s[j][2] - m1n);
            s[j][3] = __expf(s[j][3] - m1n);
            ps0 += s[j][0] + s[j][1];
            ps1 += s[j][2] + s[j][3];
            o[j][0] *= sc0; o[j][1] *= sc0;
            o[j][2] *= sc1; o[j][3] *= sc1;
        }
        ps0 += __shfl_xor_sync(0xffffffffu, ps0, 1);
        ps0 += __shfl_xor_sync(0xffffffffu, ps0, 2);
        ps1 += __shfl_xor_sync(0xffffffffu, ps1, 1);
        ps1 += __shfl_xor_sync(0xffffffffu, ps1, 2);
        l0 = l0 * sc0 + ps0;
        l1 = l1 * sc1 + ps1;
        m0 = m0n; m1 = m1n;

        // ---- O += P V (fp16) ----
        const uint32_t vbase = sb + S_V(st);
        #pragma unroll
        for (int kc = 0; kc < 4; ++kc) {
            const int j0 = 2 * kc, j1 = 2 * kc + 1;
            uint32_t a0 = f2h2(s[j0][0], s[j0][1]);
            uint32_t a1 = f2h2(s[j0][2], s[j0][3]);
            uint32_t a2 = f2h2(s[j1][0], s[j1][1]);
            uint32_t a3 = f2h2(s[j1][2], s[j1][3]);
            #pragma unroll
            for (int nfp = 0; nfp < 4; ++nfp) {
                const int nf = 2 * nfp;
                const int mrow = kc * 16 + ((lane >> 3) & 1) * 8 + (lane & 7);
                const int mcol = (nf + (lane >> 4)) * 16;
                uint32_t addr = vbase + (uint32_t)(mrow * AP + mcol);
                uint32_t r0, r1, r2, r3;
                asm volatile("ldmatrix.sync.aligned.m8n8.x4.trans.shared.b16 {%0,%1,%2,%3}, [%4];"
                    : "=r"(r0), "=r"(r1), "=r"(r2), "=r"(r3) : "r"(addr));
                MMA_F16(o[nf],     a0, a1, a2, a3, r0, r1);
                MMA_F16(o[nf + 1], a0, a1, a2, a3, r2, r3);
            }
        }
        __syncthreads();
        if (kt + 2 < NK)
            load_kv(sb, st, Khb, Klb, Vhb, (kt + 2) * 64, tid);
    }

    // ---- epilogue: normalize, split bf16, buggy layout ----
    float inv0 = 1.0f / l0, inv1 = 1.0f / l1;
    size_t r0g = ((size_t)(h * BB + b) * SS + q0 + wrow + g) * 64;
    size_t r1g = r0g + 8 * 64;
    #pragma unroll
    for (int nf = 0; nf < 8; ++nf) {
        int col = nf * 8 + qr * 2;
        float v0 = o[nf][0] * inv0, v1 = o[nf][1] * inv0;
        float v2 = o[nf][2] * inv1, v3 = o[nf][3] * inv1;
        __nv_bfloat16 h0 = __float2bfloat16_rn(v0), h1 = __float2bfloat16_rn(v1);
        __nv_bfloat16 h2 = __float2bfloat16_rn(v2), h3 = __float2bfloat16_rn(v3);
        __nv_bfloat162 H0; H0.x = h0; H0.y = h1;
        __nv_bfloat162 H1; H1.x = h2; H1.y = h3;
        __nv_bfloat162 L0, L1;
        L0.x = __float2bfloat16_rn(v0 - __bfloat162float(h0));
        L0.y = __float2bfloat16_rn(v1 - __bfloat162float(h1));
        L1.x = __float2bfloat16_rn(v2 - __bfloat162float(h2));
        L1.y = __float2bfloat16_rn(v3 - __bfloat162float(h3));
        *(__nv_bfloat162*)&Xhi[r0g + col] = H0;
        *(__nv_bfloat162*)&Xhi[r1g + col] = H1;
        *(__nv_bfloat162*)&Xlo[r0g + col] = L0;
        *(__nv_bfloat162*)&Xlo[r1g + col] = L1;
    }
}

extern "C" void kernel_launch(void* const* d_in, const int* in_sizes, int n_in,
                              void* d_out, int out_size)
{
    const float* q  = (const float*)d_in[0];
    const float* k  = (const float*)d_in[1];
    const float* v  = (const float*)d_in[2];
    const float* wq = (const float*)d_in[3];
    const float* bq = (const float*)d_in[4];
    const float* wk = (const float*)d_in[5];
    const float* bk = (const float*)d_in[6];
    const float* wv = (const float*)d_in[7];
    const float* bv = (const float*)d_in[8];
    const float* wo = (const float*)d_in[9];
    const float* bo = (const float*)d_in[10];
    float* out = (float*)d_out;

    __nv_bfloat16 *Whi, *Wlo, *Ahi, *Alo, *Qhi, *Qlo, *Khi, *Klo, *Xhi, *Xlo;
    __half *Vh;
    cudaGetSymbolAddress((void**)&Whi, g_Whi);
    cudaGetSymbolAddress((void**)&Wlo, g_Wlo);
    cudaGetSymbolAddress((void**)&Ahi, g_Ahi);
    cudaGetSymbolAddress((void**)&Alo, g_Alo);
    cudaGetSymbolAddress((void**)&Qhi, g_Qhi);
    cudaGetSymbolAddress((void**)&Qlo, g_Qlo);
    cudaGetSymbolAddress((void**)&Khi, g_Khi);
    cudaGetSymbolAddress((void**)&Klo, g_Klo);
    cudaGetSymbolAddress((void**)&Xhi, g_Xhi);
    cudaGetSymbolAddress((void**)&Xlo, g_Xlo);
    cudaGetSymbolAddress((void**)&Vh,  g_Vh);

    cudaFuncSetAttribute(gemm_split<0>, cudaFuncAttributeMaxDynamicSharedMemorySize, GEMM_SMEM);
    cudaFuncSetAttribute(gemm_split<1>, cudaFuncAttributeMaxDynamicSharedMemorySize, GEMM_SMEM);
    cudaFuncSetAttribute(gemm_split<2>, cudaFuncAttributeMaxDynamicSharedMemorySize, GEMM_SMEM);
    cudaFuncSetAttribute(attn_kernel,   cudaFuncAttributeMaxDynamicSharedMemorySize, ATTN_SMEM);

    dim3 tGrid(DD / 32, DD / 32), tBlk(32, 8);
    trans_split_kernel<<<tGrid, tBlk>>>(wq, Whi + 0*DD*DD, Wlo + 0*DD*DD);
    trans_split_kernel<<<tGrid, tBlk>>>(wk, Whi + 1*DD*DD, Wlo + 1*DD*DD);
    trans_split_kernel<<<tGrid, tBlk>>>(wv, Whi + 2*DD*DD, Wlo + 2*DD*DD);
    trans_split_kernel<<<tGrid, tBlk>>>(wo, Whi + 3*DD*DD, Wlo + 3*DD*DD);

    const int n4 = MTOT * DD / 4;
    dim3 sGrid((n4 + 255) / 256);
    dim3 gGrid(DD / 128, MTOT / 128);

    split_kernel<<<sGrid, 256>>>(q, Ahi, Alo, n4);
    gemm_split<1><<<gGrid, 256, GEMM_SMEM>>>(Ahi, Alo, Whi + 0*DD*DD, Wlo + 0*DD*DD,
                                             bq, nullptr, Qhi, Qlo, nullptr);
    split_kernel<<<sGrid, 256>>>(k, Ahi, Alo, n4);
    gemm_split<1><<<gGrid, 256, GEMM_SMEM>>>(Ahi, Alo, Whi + 1*DD*DD, Wlo + 1*DD*DD,
                                             bk, nullptr, Khi, Klo, nullptr);
    split_kernel<<<sGrid, 256>>>(v, Ahi, Alo, n4);
    gemm_split<2><<<gGrid, 256, GEMM_SMEM>>>(Ahi, Alo, Whi + 2*DD*DD, Wlo + 2*DD*DD,
                                             bv, nullptr, nullptr, nullptr, Vh);

    dim3 aGrid(SS / 128, BB * HH);
    attn_kernel<<<aGrid, 256, ATTN_SMEM>>>(Qhi, Qlo, Khi, Klo, Vh, Xhi, Xlo);

    gemm_split<0><<<gGrid, 256, GEMM_SMEM>>>(Xhi, Xlo, Whi + 3*DD*DD, Wlo + 3*DD*DD,
                                             bo, out, nullptr, nullptr, nullptr);
}

// round 7
// speedup vs baseline: 2.6693x; 1.0955x over previous
#include <cuda_runtime.h>
#include <cuda_bf16.h>
#include <cuda_fp16.h>
#include <cstdint>
#include <math.h>

#define BB 2
#define SS 2048
#define DD 1024
#define HH 16
#define DHH 64
#define MTOT (BB*SS)

__device__ __align__(256) __nv_bfloat16 g_Whi[4][DD*DD];
__device__ __align__(256) __nv_bfloat16 g_Wlo[4][DD*DD];
__device__ __align__(256) __nv_bfloat16 g_Ahi[3][MTOT*DD];
__device__ __align__(256) __nv_bfloat16 g_Alo[3][MTOT*DD];
__device__ __align__(256) __nv_bfloat16 g_Qhi[MTOT*DD];
__device__ __align__(256) __nv_bfloat16 g_Qlo[MTOT*DD];
__device__ __align__(256) __nv_bfloat16 g_Khi[MTOT*DD];
__device__ __align__(256) __nv_bfloat16 g_Klo[MTOT*DD];
__device__ __align__(256) __half        g_Vh [MTOT*DD];
__device__ __align__(256) __nv_bfloat16 g_Xhi[MTOT*DD];
__device__ __align__(256) __nv_bfloat16 g_Xlo[MTOT*DD];

__device__ __forceinline__ uint32_t smem_u32(const void* p) {
    uint32_t a;
    asm("{ .reg .u64 t; cvta.to.shared.u64 t, %1; cvt.u32.u64 %0, t; }" : "=r"(a) : "l"(p));
    return a;
}
__device__ __forceinline__ void cp_async16(uint32_t dst, const void* src) {
    asm volatile("cp.async.cg.shared.global [%0], [%1], 16;" :: "r"(dst), "l"(src));
}
#define CP_COMMIT() asm volatile("cp.async.commit_group;" ::: "memory")

#define MMA_BF16(c, a, b0, b1) \
    asm volatile("mma.sync.aligned.m16n8k16.row.col.f32.bf16.bf16.f32 " \
        "{%0,%1,%2,%3}, {%4,%5,%6,%7}, {%8,%9}, {%0,%1,%2,%3};" \
        : "+f"((c)[0]), "+f"((c)[1]), "+f"((c)[2]), "+f"((c)[3]) \
        : "r"((a)[0]), "r"((a)[1]), "r"((a)[2]), "r"((a)[3]), "r"(b0), "r"(b1))

#define MMA_F16(c, a0, a1, a2, a3, b0, b1) \
    asm volatile("mma.sync.aligned.m16n8k16.row.col.f32.f16.f16.f32 " \
        "{%0,%1,%2,%3}, {%4,%5,%6,%7}, {%8,%9}, {%0,%1,%2,%3};" \
        : "+f"((c)[0]), "+f"((c)[1]), "+f"((c)[2]), "+f"((c)[3]) \
        : "r"(a0), "r"(a1), "r"(a2), "r"(a3), "r"(b0), "r"(b1))

#define LDM_X4(r, a) \
    asm volatile("ldmatrix.sync.aligned.m8n8.x4.shared.b16 {%0,%1,%2,%3}, [%4];" \
        : "=r"((r)[0]), "=r"((r)[1]), "=r"((r)[2]), "=r"((r)[3]) : "r"(a))

__device__ __forceinline__ uint32_t f2h2(float x, float y) {
    __half2 t = __floats2half2_rn(x, y);
    return *(uint32_t*)&t;
}

// ============ fused weight transpose + split (z = which weight) ============
__global__ __launch_bounds__(256) void trans_split_kernel(
    const float* __restrict__ w0, const float* __restrict__ w1,
    const float* __restrict__ w2, const float* __restrict__ w3,
    __nv_bfloat16* __restrict__ hi_base, __nv_bfloat16* __restrict__ lo_base)
{
    const float* in = (blockIdx.z == 0) ? w0 : (blockIdx.z == 1) ? w1
                     : (blockIdx.z == 2) ? w2 : w3;
    __nv_bfloat16* hi = hi_base + (size_t)blockIdx.z * DD * DD;
    __nv_bfloat16* lo = lo_base + (size_t)blockIdx.z * DD * DD;
    __shared__ float t[32][33];
    int x = blockIdx.x * 32 + threadIdx.x;
    int y = blockIdx.y * 32 + threadIdx.y;
    #pragma unroll
    for (int j = 0; j < 32; j += 8)
        t[threadIdx.y + j][threadIdx.x] = in[(size_t)(y + j) * DD + x];
    __syncthreads();
    int x2 = blockIdx.y * 32 + threadIdx.x;
    int y2 = blockIdx.x * 32 + threadIdx.y;
    #pragma unroll
    for (int j = 0; j < 32; j += 8) {
        float w = t[threadIdx.x][threadIdx.y + j];
        __nv_bfloat16 h = __float2bfloat16_rn(w);
        hi[(size_t)(y2 + j) * DD + x2] = h;
        lo[(size_t)(y2 + j) * DD + x2] = __float2bfloat16_rn(w - __bfloat162float(h));
    }
}

// ============ fused activation split (z = q/k/v) ============
__global__ __launch_bounds__(256) void split_kernel(
    const float* __restrict__ a0, const float* __restrict__ a1,
    const float* __restrict__ a2,
    __nv_bfloat16* __restrict__ hi_base, __nv_bfloat16* __restrict__ lo_base, int n4)
{
    int i = blockIdx.x * blockDim.x + threadIdx.x;
    if (i >= n4) return;
    const float* a = (blockIdx.z == 0) ? a0 : (blockIdx.z == 1) ? a1 : a2;
    __nv_bfloat16* hi = hi_base + (size_t)blockIdx.z * MTOT * DD;
    __nv_bfloat16* lo = lo_base + (size_t)blockIdx.z * MTOT * DD;
    float4 v = ((const float4*)a)[i];
    __nv_bfloat16 hx = __float2bfloat16_rn(v.x), hy = __float2bfloat16_rn(v.y);
    __nv_bfloat16 hz = __float2bfloat16_rn(v.z), hw = __float2bfloat16_rn(v.w);
    __nv_bfloat162 h0; h0.x = hx; h0.y = hy;
    __nv_bfloat162 h1; h1.x = hz; h1.y = hw;
    __nv_bfloat162 l0, l1;
    l0.x = __float2bfloat16_rn(v.x - __bfloat162float(hx));
    l0.y = __float2bfloat16_rn(v.y - __bfloat162float(hy));
    l1.x = __float2bfloat16_rn(v.z - __bfloat162float(hz));
    l1.y = __float2bfloat16_rn(v.w - __bfloat162float(hw));
    ((__nv_bfloat162*)hi)[i*2+0] = h0; ((__nv_bfloat162*)hi)[i*2+1] = h1;
    ((__nv_bfloat162*)lo)[i*2+0] = l0; ((__nv_bfloat162*)lo)[i*2+1] = l1;
}

// ============ split-bf16 GEMM core: 2-stage, occ 2, ldmatrix ============
#define PITCH   80
#define T_AH    0
#define T_AL    10240
#define T_BH    20480
#define T_BL    30720
#define STAGE   40960
#define GEMM_SMEM (2*STAGE)

__device__ __forceinline__ void load_chunk_g(
    uint32_t sbase, int st,
    const __nv_bfloat16* __restrict__ Ah, const __nv_bfloat16* __restrict__ Al,
    const __nv_bfloat16* __restrict__ Bh, const __nv_bfloat16* __restrict__ Bl,
    int bm, int bn, int k0, int tid)
{
    uint32_t s = sbase + st * STAGE;
    #pragma unroll
    for (int it = 0; it < 2; ++it) {
        int idx = tid + it * 256;
        int row = idx >> 2, qq = idx & 3;
        uint32_t doff = (uint32_t)(row * PITCH + qq * 16);
        size_t ga = (size_t)(bm + row) * DD + k0 + qq * 8;
        size_t gb = (size_t)(bn + row) * DD + k0 + qq * 8;
        cp_async16(s + T_AH + doff, Ah + ga);
        cp_async16(s + T_AL + doff, Al + ga);
        cp_async16(s + T_BH + doff, Bh + gb);
        cp_async16(s + T_BL + doff, Bl + gb);
    }
    CP_COMMIT();
}

// Core mainloop: accumulates c[4][4][4] for (bm, bn_local) over the given A/B.
__device__ __forceinline__ void gemm_core(
    uint32_t sbase, const __nv_bfloat16* Ah, const __nv_bfloat16* Al,
    const __nv_bfloat16* Bh, const __nv_bfloat16* Bl,
    int bm, int bn, int tid, int lane, int warp_m, int warp_n,
    float c[4][4][4])
{
    const uint32_t a_off = (uint32_t)((warp_m * 64 + (lane & 15)) * PITCH + ((lane >> 4) << 4));
    const uint32_t b_off = (uint32_t)((warp_n * 32 + ((lane >> 4) << 3) + (lane & 7)) * PITCH
                                      + (((lane >> 3) & 1) << 4));
    load_chunk_g(sbase, 0, Ah, Al, Bh, Bl, bm, bn, 0,  tid);
    load_chunk_g(sbase, 1, Ah, Al, Bh, Bl, bm, bn, 32, tid);

    const int NCHUNK = DD / 32;
    for (int i = 0; i < NCHUNK; ++i) {
        const int st = i & 1;
        if (i < NCHUNK - 1) asm volatile("cp.async.wait_group 1;" ::: "memory");
        else                asm volatile("cp.async.wait_group 0;" ::: "memory");
        __syncthreads();

        const uint32_t stb = sbase + st * STAGE;
        #pragma unroll
        for (int ks = 0; ks < 2; ++ks) {
            const uint32_t kb = ks * 32;
            uint32_t ah[4][4], al[4][4], bh[2][4], bl[2][4];
            #pragma unroll
            for (int mf = 0; mf < 4; ++mf) {
                uint32_t ra = stb + T_AH + a_off + mf * (16 * PITCH) + kb;
                LDM_X4(ah[mf], ra);
                LDM_X4(al[mf], ra + (T_AL - T_AH));
            }
            #pragma unroll
            for (int p = 0; p < 2; ++p) {
                uint32_t rb = stb + T_BH + b_off + p * (16 * PITCH) + kb;
                LDM_X4(bh[p], rb);
                LDM_X4(bl[p], rb + (T_BL - T_BH));
            }
            #pragma unroll
            for (int mf = 0; mf < 4; ++mf)
                #pragma unroll
                for (int nf = 0; nf < 4; ++nf) {
                    const int p = nf >> 1, hh = (nf & 1) * 2;
                    MMA_BF16(c[mf][nf], ah[mf], bh[p][hh], bh[p][hh+1]);
                    MMA_BF16(c[mf][nf], ah[mf], bl[p][hh], bl[p][hh+1]);
                    MMA_BF16(c[mf][nf], al[mf], bh[p][hh], bh[p][hh+1]);
                }
        }
        __syncthreads();
        if (i + 2 < NCHUNK)
            load_chunk_g(sbase, st, Ah, Al, Bh, Bl, bm, bn, (i + 2) * 32, tid);
    }
}

// Fused Q/K/V projections: grid (24, 32); proj = blockIdx.x>>3.
__global__ __launch_bounds__(256, 2) void qkv_gemm(
    const __nv_bfloat16* __restrict__ Ahi_all, const __nv_bfloat16* __restrict__ Alo_all,
    const __nv_bfloat16* __restrict__ Whi_all, const __nv_bfloat16* __restrict__ Wlo_all,
    const float* __restrict__ bq, const float* __restrict__ bk, const float* __restrict__ bv,
    __nv_bfloat16* __restrict__ Qhi, __nv_bfloat16* __restrict__ Qlo,
    __nv_bfloat16* __restrict__ Khi, __nv_bfloat16* __restrict__ Klo,
    __half* __restrict__ Vh)
{
    extern __shared__ char smem[];
    const uint32_t sbase = smem_u32(smem);
    const int tid = threadIdx.x, wid = tid >> 5, lane = tid & 31;
    const int warp_m = wid & 1, warp_n = wid >> 1;
    const int proj = blockIdx.x >> 3;
    const int bn = (blockIdx.x & 7) * 128;
    const int bm = blockIdx.y * 128;

    const __nv_bfloat16* Ah = Ahi_all + (size_t)proj * MTOT * DD;
    const __nv_bfloat16* Al = Alo_all + (size_t)proj * MTOT * DD;
    const __nv_bfloat16* Bh = Whi_all + (size_t)proj * DD * DD;
    const __nv_bfloat16* Bl = Wlo_all + (size_t)proj * DD * DD;
    const float* bias = (proj == 0) ? bq : (proj == 1) ? bk : bv;

    float c[4][4][4];
    #pragma unroll
    for (int i = 0; i < 4; ++i)
        #pragma unroll
        for (int j = 0; j < 4; ++j)
            #pragma unroll
            for (int e = 0; e < 4; ++e) c[i][j][e] = 0.f;

    gemm_core(sbase, Ah, Al, Bh, Bl, bm, bn, tid, lane, warp_m, warp_n, c);

    __nv_bfloat16* Oh = (proj == 0) ? Qhi : Khi;
    __nv_bfloat16* Ol = (proj == 0) ? Qlo : Klo;

    #pragma unroll
    for (int mf = 0; mf < 4; ++mf) {
        int m0 = bm + warp_m * 64 + mf * 16 + (lane >> 2);
        #pragma unroll
        for (int nf = 0; nf < 4; ++nf) {
            int n = bn + warp_n * 32 + nf * 8 + (lane & 3) * 2;
            float2 bb = *(const float2*)&bias[n];
            float v0 = c[mf][nf][0] + bb.x, v1 = c[mf][nf][1] + bb.y;
            float v2 = c[mf][nf][2] + bb.x, v3 = c[mf][nf][3] + bb.y;
            size_t i0 = (size_t)m0 * DD + n, i1 = (size_t)(m0 + 8) * DD + n;
            if (proj == 2) {
                *(__half2*)&Vh[i0] = __floats2half2_rn(v0, v1);
                *(__half2*)&Vh[i1] = __floats2half2_rn(v2, v3);
            } else {
                __nv_bfloat16 h0 = __float2bfloat16_rn(v0), h1 = __float2bfloat16_rn(v1);
                __nv_bfloat16 h2 = __float2bfloat16_rn(v2), h3 = __float2bfloat16_rn(v3);
                __nv_bfloat162 H0; H0.x = h0; H0.y = h1;
                __nv_bfloat162 H1; H1.x = h2; H1.y = h3;
                __nv_bfloat162 L0, L1;
                L0.x = __float2bfloat16_rn(v0 - __bfloat162float(h0));
                L0.y = __float2bfloat16_rn(v1 - __bfloat162float(h1));
                L1.x = __float2bfloat16_rn(v2 - __bfloat162float(h2));
                L1.y = __float2bfloat16_rn(v3 - __bfloat162float(h3));
                *(__nv_bfloat162*)&Oh[i0] = H0; *(__nv_bfloat162*)&Oh[i1] = H1;
                *(__nv_bfloat162*)&Ol[i0] = L0; *(__nv_bfloat162*)&Ol[i1] = L1;
            }
        }
    }
}

// Output projection: fp32 + bias.
__global__ __launch_bounds__(256, 2) void out_gemm(
    const __nv_bfloat16* __restrict__ Ah, const __nv_bfloat16* __restrict__ Al,
    const __nv_bfloat16* __restrict__ Bh, const __nv_bfloat16* __restrict__ Bl,
    const float* __restrict__ bias, float* __restrict__ C)
{
    extern __shared__ char smem[];
    const uint32_t sbase = smem_u32(smem);
    const int tid = threadIdx.x, wid = tid >> 5, lane = tid & 31;
    const int warp_m = wid & 1, warp_n = wid >> 1;
    const int bm = blockIdx.y * 128, bn = blockIdx.x * 128;

    float c[4][4][4];
    #pragma unroll
    for (int i = 0; i < 4; ++i)
        #pragma unroll
        for (int j = 0; j < 4; ++j)
            #pragma unroll
            for (int e = 0; e < 4; ++e) c[i][j][e] = 0.f;

    gemm_core(sbase, Ah, Al, Bh, Bl, bm, bn, tid, lane, warp_m, warp_n, c);

    #pragma unroll
    for (int mf = 0; mf < 4; ++mf) {
        int m0 = bm + warp_m * 64 + mf * 16 + (lane >> 2);
        #pragma unroll
        for (int nf = 0; nf < 4; ++nf) {
            int n = bn + warp_n * 32 + nf * 8 + (lane & 3) * 2;
            float2 bb = *(const float2*)&bias[n];
            *(float2*)&C[(size_t)m0 * DD + n] =
                make_float2(c[mf][nf][0] + bb.x, c[mf][nf][1] + bb.y);
            *(float2*)&C[(size_t)(m0 + 8) * DD + n] =
                make_float2(c[mf][nf][2] + bb.x, c[mf][nf][3] + bb.y);
        }
    }
}

// ============ tensor-core flash attention (unchanged from round 6) ============
#define AP 144
#define S_QH 0
#define S_QL (128*AP)
#define S_KH(st) (2*128*AP + (st)*3*64*AP)
#define S_KL(st) (S_KH(st) + 64*AP)
#define S_V(st)  (S_KH(st) + 2*64*AP)
#define ATTN_SMEM (2*128*AP + 2*3*64*AP)

__device__ __forceinline__ void load_kv(uint32_t sb, int st,
    const char* Khb, const char* Klb, const char* Vhb, int key0, int tid)
{
    uint32_t kh = sb + S_KH(st), kl = sb + S_KL(st), vv = sb + S_V(st);
    #pragma unroll
    for (int p = 0; p < 2; ++p) {
        int id = tid + p * 256;
        int row = id >> 3, c = id & 7;
        size_t go = (size_t)(key0 + row) * (DD * 2) + c * 16;
        uint32_t so = (uint32_t)(row * AP + c * 16);
        cp_async16(kh + so, Khb + go);
        cp_async16(kl + so, Klb + go);
        cp_async16(vv + so, Vhb + go);
    }
    CP_COMMIT();
}

__global__ __launch_bounds__(256, 2) void attn_kernel(
    const __nv_bfloat16* __restrict__ Qh, const __nv_bfloat16* __restrict__ Ql,
    const __nv_bfloat16* __restrict__ Kh, const __nv_bfloat16* __restrict__ Kl,
    const __half* __restrict__ Vv,
    __nv_bfloat16* __restrict__ Xhi, __nv_bfloat16* __restrict__ Xlo)
{
    extern __shared__ char sm[];
    const uint32_t sb = smem_u32(sm);
    const int tid = threadIdx.x, lane = tid & 31, w = tid >> 5;
    const int q0 = blockIdx.x * 128;
    const int b = blockIdx.y >> 4, h = blockIdx.y & 15;
    const int g = lane >> 2, qr = lane & 3;
    const int wrow = w * 16;

    const char* Qhb = (const char*)(Qh + (size_t)b * SS * DD + h * 64);
    const char* Qlb = (const char*)(Ql + (size_t)b * SS * DD + h * 64);
    const char* Khb = (const char*)(Kh + (size_t)b * SS * DD + h * 64);
    const char* Klb = (const char*)(Kl + (size_t)b * SS * DD + h * 64);
    const char* Vhb = (const char*)(Vv + (size_t)b * SS * DD + h * 64);

    #pragma unroll
    for (int p = 0; p < 4; ++p) {
        int id = tid + p * 256;
        int row = id >> 3, c = id & 7;
        size_t go = (size_t)(q0 + row) * (DD * 2) + c * 16;
        uint32_t so = (uint32_t)(row * AP + c * 16);
        cp_async16(sb + S_QH + so, Qhb + go);
        cp_async16(sb + S_QL + so, Qlb + go);
    }
    CP_COMMIT();
    load_kv(sb, 0, Khb, Klb, Vhb, 0, tid);
    load_kv(sb, 1, Khb, Klb, Vhb, 64, tid);

    asm volatile("cp.async.wait_group 2;" ::: "memory");
    __syncthreads();
    const uint32_t q_off = (uint32_t)((wrow + (lane & 15)) * AP + ((lane >> 4) << 4));
    uint32_t qh[4][4], ql[4][4];
    #pragma unroll
    for (int kc = 0; kc < 4; ++kc) {
        uint32_t ra = sb + S_QH + q_off + kc * 32;
        LDM_X4(qh[kc], ra);
        LDM_X4(ql[kc], ra + (S_QL - S_QH));
    }

    const uint32_t k_off = (uint32_t)((((lane >> 4) << 3) + (lane & 7)) * AP
                                      + (((lane >> 3) & 1) << 4));

    float m0 = -1e30f, m1 = -1e30f, l0 = 0.f, l1 = 0.f;
    float o[8][4];
    #pragma unroll
    for (int j = 0; j < 8; ++j)
        #pragma unroll
        for (int e = 0; e < 4; ++e) o[j][e] = 0.f;

    const int NK = SS / 64;
    for (int kt = 0; kt < NK; ++kt) {
        const int st = kt & 1;
        if (kt < NK - 1) asm volatile("cp.async.wait_group 1;" ::: "memory");
        else             asm volatile("cp.async.wait_group 0;" ::: "memory");
        __syncthreads();

        const uint32_t KHb = sb + S_KH(st);

        float s[8][4];
        #pragma unroll
        for (int j = 0; j < 8; ++j)
            #pragma unroll
            for (int e = 0; e < 4; ++e) s[j][e] = 0.f;

        #pragma unroll
        for (int kc = 0; kc < 4; ++kc) {
            #pragma unroll
            for (int p = 0; p < 4; ++p) {
                uint32_t rb = KHb + k_off + p * (16 * AP) + kc * 32;
                uint32_t kh4[4], kl4[4];
                LDM_X4(kh4, rb);
                LDM_X4(kl4, rb + 64 * AP);
                MMA_BF16(s[2*p],   qh[kc], kh4[0], kh4[1]);
                MMA_BF16(s[2*p],   qh[kc], kl4[0], kl4[1]);
                MMA_BF16(s[2*p],   ql[kc], kh4[0], kh4[1]);
                MMA_BF16(s[2*p+1], qh[kc], kh4[2], kh4[3]);
                MMA_BF16(s[2*p+1], qh[kc], kl4[2], kl4[3]);
                MMA_BF16(s[2*p+1], ql[kc], kh4[2], kh4[3]);
            }
        }

        float mx0 = -1e30f, mx1 = -1e30f;
        #pragma unroll
        for (int j = 0; j < 8; ++j) {
            mx0 = fmaxf(mx0, fmaxf(s[j][0], s[j][1]));
            mx1 = fmaxf(mx1, fmaxf(s[j][2], s[j][3]));
        }
        mx0 = fmaxf(mx0, __shfl_xor_sync(0xffffffffu, mx0, 1));
        mx0 = fmaxf(mx0, __shfl_xor_sync(0xffffffffu, mx0, 2));
        mx1 = fmaxf(mx1, __shfl_xor_sync(0xffffffffu, mx1, 1));
        mx1 = fmaxf(mx1, __shfl_xor_sync(0xffffffffu, mx1, 2));
        float m0n = fmaxf(m0, mx0), m1n = fmaxf(m1, mx1);
        float sc0 = __expf(m0 - m0n), sc1 = __expf(m1 - m1n);
        float ps0 = 0.f, ps1 = 0.f;
        #pragma unroll
        for (int j = 0; j < 8; ++j) {
            s[j][0] = __expf(s[j][0] - m0n);
            s[j][1] = __expf(s[j][1] - m0n);
            s[j][2] = __expf(s[j][2] - m1n);
            s[j][3] = __expf(s[j][3] - m1n);
            ps0 += s[j][0] + s[j][1];
            ps1 += s[j][2] + s[j][3];
            o[j][0] *= sc0; o[j][1] *= sc0;
            o[j][2] *= sc1; o[j][3] *= sc1;
        }
        ps0 += __shfl_xor_sync(0xffffffffu, ps0, 1);
        ps0 += __shfl_xor_sync(0xffffffffu, ps0, 2);
        ps1 += __shfl_xor_sync(0xffffffffu, ps1, 1);
        ps1 += __shfl_xor_sync(0xffffffffu, ps1, 2);
        l0 = l0 * sc0 + ps0;
        l1 = l1 * sc1 + ps1;
        m0 = m0n; m1 = m1n;

        const uint32_t vbase = sb + S_V(st);
        #pragma unroll
        for (int kc = 0; kc < 4; ++kc) {
            const int j0 = 2 * kc, j1 = 2 * kc + 1;
            uint32_t a0 = f2h2(s[j0][0], s[j0][1]);
            uint32_t a1 = f2h2(s[j0][2], s[j0][3]);
            uint32_t a2 = f2h2(s[j1][0], s[j1][1]);
            uint32_t a3 = f2h2(s[j1][2], s[j1][3]);
            #pragma unroll
            for (int nfp = 0; nfp < 4; ++nfp) {
                const int nf = 2 * nfp;
                const int mrow = kc * 16 + ((lane >> 3) & 1) * 8 + (lane & 7);
                const int mcol = (nf + (lane >> 4)) * 16;
                uint32_t addr = vbase + (uint32_t)(mrow * AP + mcol);
                uint32_t r0, r1, r2, r3;
                asm volatile("ldmatrix.sync.aligned.m8n8.x4.trans.shared.b16 {%0,%1,%2,%3}, [%4];"
                    : "=r"(r0), "=r"(r1), "=r"(r2), "=r"(r3) : "r"(addr));
                MMA_F16(o[nf],     a0, a1, a2, a3, r0, r1);
                MMA_F16(o[nf + 1], a0, a1, a2, a3, r2, r3);
            }
        }
        __syncthreads();
        if (kt + 2 < NK)
            load_kv(sb, st, Khb, Klb, Vhb, (kt + 2) * 64, tid);
    }

    float inv0 = 1.0f / l0, inv1 = 1.0f / l1;
    size_t r0g = ((size_t)(h * BB + b) * SS + q0 + wrow + g) * 64;
    size_t r1g = r0g + 8 * 64;
    #pragma unroll
    for (int nf = 0; nf < 8; ++nf) {
        int col = nf * 8 + qr * 2;
        float v0 = o[nf][0] * inv0, v1 = o[nf][1] * inv0;
        float v2 = o[nf][2] * inv1, v3 = o[nf][3] * inv1;
        __nv_bfloat16 h0 = __float2bfloat16_rn(v0), h1 = __float2bfloat16_rn(v1);
        __nv_bfloat16 h2 = __float2bfloat16_rn(v2), h3 = __float2bfloat16_rn(v3);
        __nv_bfloat162 H0; H0.x = h0; H0.y = h1;
        __nv_bfloat162 H1; H1.x = h2; H1.y = h3;
        __nv_bfloat162 L0, L1;
        L0.x = __float2bfloat16_rn(v0 - __bfloat162float(h0));
        L0.y = __float2bfloat16_rn(v1 - __bfloat162float(h1));
        L1.x = __float2bfloat16_rn(v2 - __bfloat162float(h2));
        L1.y = __float2bfloat16_rn(v3 - __bfloat162float(h3));
        *(__nv_bfloat162*)&Xhi[r0g + col] = H0;
        *(__nv_bfloat162*)&Xhi[r1g + col] = H1;
        *(__nv_bfloat162*)&Xlo[r0g + col] = L0;
        *(__nv_bfloat162*)&Xlo[r1g + col] = L1;
    }
}

extern "C" void kernel_launch(void* const* d_in, const int* in_sizes, int n_in,
                              void* d_out, int out_size)
{
    const float* q  = (const float*)d_in[0];
    const float* k  = (const float*)d_in[1];
    const float* v  = (const float*)d_in[2];
    const float* wq = (const float*)d_in[3];
    const float* bq = (const float*)d_in[4];
    const float* wk = (const float*)d_in[5];
    const float* bk = (const float*)d_in[6];
    const float* wv = (const float*)d_in[7];
    const float* bv = (const float*)d_in[8];
    const float* wo = (const float*)d_in[9];
    const float* bo = (const float*)d_in[10];
    float* out = (float*)d_out;

    __nv_bfloat16 *Whi, *Wlo, *Ahi, *Alo, *Qhi, *Qlo, *Khi, *Klo, *Xhi, *Xlo;
    __half *Vh;
    cudaGetSymbolAddress((void**)&Whi, g_Whi);
    cudaGetSymbolAddress((void**)&Wlo, g_Wlo);
    cudaGetSymbolAddress((void**)&Ahi, g_Ahi);
    cudaGetSymbolAddress((void**)&Alo, g_Alo);
    cudaGetSymbolAddress((void**)&Qhi, g_Qhi);
    cudaGetSymbolAddress((void**)&Qlo, g_Qlo);
    cudaGetSymbolAddress((void**)&Khi, g_Khi);
    cudaGetSymbolAddress((void**)&Klo, g_Klo);
    cudaGetSymbolAddress((void**)&Xhi, g_Xhi);
    cudaGetSymbolAddress((void**)&Xlo, g_Xlo);
    cudaGetSymbolAddress((void**)&Vh,  g_Vh);

    cudaFuncSetAttribute(qkv_gemm,    cudaFuncAttributeMaxDynamicSharedMemorySize, GEMM_SMEM);
    cudaFuncSetAttribute(out_gemm,    cudaFuncAttributeMaxDynamicSharedMemorySize, GEMM_SMEM);
    cudaFuncSetAttribute(attn_kernel, cudaFuncAttributeMaxDynamicSharedMemorySize, ATTN_SMEM);

    // fused weight transposes (z = 4)
    dim3 tGrid(DD / 32, DD / 32, 4), tBlk(32, 8);
    trans_split_kernel<<<tGrid, tBlk>>>(wq, wk, wv, wo, Whi, Wlo);

    // fused activation splits (z = 3)
    const int n4 = MTOT * DD / 4;
    dim3 sGrid((n4 + 255) / 256, 1, 3);
    split_kernel<<<sGrid, 256>>>(q, k, v, Ahi, Alo, n4);

    // fused Q/K/V projections
    dim3 qkvGrid(24, MTOT / 128);
    qkv_gemm<<<qkvGrid, 256, GEMM_SMEM>>>(Ahi, Alo, Whi, Wlo, bq, bk, bv,
                                          Qhi, Qlo, Khi, Klo, Vh);

    // attention
    dim3 aGrid(SS / 128, BB * HH);
    attn_kernel<<<aGrid, 256, ATTN_SMEM>>>(Qhi, Qlo, Khi, Klo, Vh, Xhi, Xlo);

    // output projection
    dim3 oGrid(DD / 128, MTOT / 128);
    out_gemm<<<oGrid, 256, GEMM_SMEM>>>(Xhi, Xlo, Whi + 3*(size_t)DD*DD, Wlo + 3*(size_t)DD*DD,
                                        bo, out);
}

// round 8
// speedup vs baseline: 2.9269x; 1.0965x over previous
#include <cuda_runtime.h>
#include <cuda_bf16.h>
#include <cuda_fp16.h>
#include <cstdint>
#include <math.h>

#define BB 2
#define SS 2048
#define DD 1024
#define HH 16
#define DHH 64
#define MTOT (BB*SS)

__device__ __align__(256) __nv_bfloat16 g_Whi[4][DD*DD];
__device__ __align__(256) __nv_bfloat16 g_Wlo[4][DD*DD];
__device__ __align__(256) __nv_bfloat16 g_Ahi[3][MTOT*DD];
__device__ __align__(256) __nv_bfloat16 g_Alo[3][MTOT*DD];
__device__ __align__(256) __nv_bfloat16 g_Qhi[MTOT*DD];
__device__ __align__(256) __nv_bfloat16 g_Qlo[MTOT*DD];
__device__ __align__(256) __nv_bfloat16 g_Khi[MTOT*DD];
__device__ __align__(256) __nv_bfloat16 g_Klo[MTOT*DD];
__device__ __align__(256) __half        g_Vh [MTOT*DD];
__device__ __align__(256) __nv_bfloat16 g_Xhi[MTOT*DD];
__device__ __align__(256) __nv_bfloat16 g_Xlo[MTOT*DD];

__device__ __forceinline__ uint32_t smem_u32(const void* p) {
    uint32_t a;
    asm("{ .reg .u64 t; cvta.to.shared.u64 t, %1; cvt.u32.u64 %0, t; }" : "=r"(a) : "l"(p));
    return a;
}
__device__ __forceinline__ void cp_async16(uint32_t dst, const void* src) {
    asm volatile("cp.async.cg.shared.global [%0], [%1], 16;" :: "r"(dst), "l"(src));
}
#define CP_COMMIT() asm volatile("cp.async.commit_group;" ::: "memory")

#define MMA_BF16(c, a, b0, b1) \
    asm volatile("mma.sync.aligned.m16n8k16.row.col.f32.bf16.bf16.f32 " \
        "{%0,%1,%2,%3}, {%4,%5,%6,%7}, {%8,%9}, {%0,%1,%2,%3};" \
        : "+f"((c)[0]), "+f"((c)[1]), "+f"((c)[2]), "+f"((c)[3]) \
        : "r"((a)[0]), "r"((a)[1]), "r"((a)[2]), "r"((a)[3]), "r"(b0), "r"(b1))

#define MMA_F16(c, a0, a1, a2, a3, b0, b1) \
    asm volatile("mma.sync.aligned.m16n8k16.row.col.f32.f16.f16.f32 " \
        "{%0,%1,%2,%3}, {%4,%5,%6,%7}, {%8,%9}, {%0,%1,%2,%3};" \
        : "+f"((c)[0]), "+f"((c)[1]), "+f"((c)[2]), "+f"((c)[3]) \
        : "r"(a0), "r"(a1), "r"(a2), "r"(a3), "r"(b0), "r"(b1))

#define LDM_X4(r, a) \
    asm volatile("ldmatrix.sync.aligned.m8n8.x4.shared.b16 {%0,%1,%2,%3}, [%4];" \
        : "=r"((r)[0]), "=r"((r)[1]), "=r"((r)[2]), "=r"((r)[3]) : "r"(a))

__device__ __forceinline__ uint32_t f2h2(float x, float y) {
    __half2 t = __floats2half2_rn(x, y);
    return *(uint32_t*)&t;
}

// ============ fused weight transpose + split ============
__global__ __launch_bounds__(256) void trans_split_kernel(
    const float* __restrict__ w0, const float* __restrict__ w1,
    const float* __restrict__ w2, const float* __restrict__ w3,
    __nv_bfloat16* __restrict__ hi_base, __nv_bfloat16* __restrict__ lo_base)
{
    const float* in = (blockIdx.z == 0) ? w0 : (blockIdx.z == 1) ? w1
                     : (blockIdx.z == 2) ? w2 : w3;
    __nv_bfloat16* hi = hi_base + (size_t)blockIdx.z * DD * DD;
    __nv_bfloat16* lo = lo_base + (size_t)blockIdx.z * DD * DD;
    __shared__ float t[32][33];
    int x = blockIdx.x * 32 + threadIdx.x;
    int y = blockIdx.y * 32 + threadIdx.y;
    #pragma unroll
    for (int j = 0; j < 32; j += 8)
        t[threadIdx.y + j][threadIdx.x] = in[(size_t)(y + j) * DD + x];
    __syncthreads();
    int x2 = blockIdx.y * 32 + threadIdx.x;
    int y2 = blockIdx.x * 32 + threadIdx.y;
    #pragma unroll
    for (int j = 0; j < 32; j += 8) {
        float w = t[threadIdx.x][threadIdx.y + j];
        __nv_bfloat16 h = __float2bfloat16_rn(w);
        hi[(size_t)(y2 + j) * DD + x2] = h;
        lo[(size_t)(y2 + j) * DD + x2] = __float2bfloat16_rn(w - __bfloat162float(h));
    }
}

// ============ fused activation split ============
__global__ __launch_bounds__(256) void split_kernel(
    const float* __restrict__ a0, const float* __restrict__ a1,
    const float* __restrict__ a2,
    __nv_bfloat16* __restrict__ hi_base, __nv_bfloat16* __restrict__ lo_base, int n4)
{
    int i = blockIdx.x * blockDim.x + threadIdx.x;
    if (i >= n4) return;
    const float* a = (blockIdx.z == 0) ? a0 : (blockIdx.z == 1) ? a1 : a2;
    __nv_bfloat16* hi = hi_base + (size_t)blockIdx.z * MTOT * DD;
    __nv_bfloat16* lo = lo_base + (size_t)blockIdx.z * MTOT * DD;
    float4 v = ((const float4*)a)[i];
    __nv_bfloat16 hx = __float2bfloat16_rn(v.x), hy = __float2bfloat16_rn(v.y);
    __nv_bfloat16 hz = __float2bfloat16_rn(v.z), hw = __float2bfloat16_rn(v.w);
    __nv_bfloat162 h0; h0.x = hx; h0.y = hy;
    __nv_bfloat162 h1; h1.x = hz; h1.y = hw;
    __nv_bfloat162 l0, l1;
    l0.x = __float2bfloat16_rn(v.x - __bfloat162float(hx));
    l0.y = __float2bfloat16_rn(v.y - __bfloat162float(hy));
    l1.x = __float2bfloat16_rn(v.z - __bfloat162float(hz));
    l1.y = __float2bfloat16_rn(v.w - __bfloat162float(hw));
    ((__nv_bfloat162*)hi)[i*2+0] = h0; ((__nv_bfloat162*)hi)[i*2+1] = h1;
    ((__nv_bfloat162*)lo)[i*2+0] = l0; ((__nv_bfloat162*)lo)[i*2+1] = l1;
}

// ============ split-bf16 GEMM: 3-stage, occ 2, swizzled 64B rows ============
// tile = 128 rows x 64B (k=32 bf16), unit swizzle: c ^= (row>>1)&3
#define T_AH    0
#define T_AL    8192
#define T_BH    16384
#define T_BL    24576
#define STAGE   32768
#define GEMM_SMEM (3*STAGE)

__device__ __forceinline__ void load_chunk_g(
    uint32_t sbase, int st,
    const __nv_bfloat16* __restrict__ Ah, const __nv_bfloat16* __restrict__ Al,
    const __nv_bfloat16* __restrict__ Bh, const __nv_bfloat16* __restrict__ Bl,
    int bm, int bn, int k0, int tid)
{
    uint32_t s = sbase + st * STAGE;
    #pragma unroll
    for (int it = 0; it < 2; ++it) {
        int idx = tid + it * 256;          // 0..511
        int row = idx >> 2, q = idx & 3;
        int qs = q ^ ((row >> 1) & 3);
        uint32_t doff = (uint32_t)(row * 64 + qs * 16);
        size_t ga = (size_t)(bm + row) * DD + k0 + q * 8;
        size_t gb = (size_t)(bn + row) * DD + k0 + q * 8;
        cp_async16(s + T_AH + doff, Ah + ga);
        cp_async16(s + T_AL + doff, Al + ga);
        cp_async16(s + T_BH + doff, Bh + gb);
        cp_async16(s + T_BL + doff, Bl + gb);
    }
    CP_COMMIT();
}

__device__ __forceinline__ void gemm_core(
    uint32_t sbase, const __nv_bfloat16* Ah, const __nv_bfloat16* Al,
    const __nv_bfloat16* Bh, const __nv_bfloat16* Bl,
    int bm, int bn, int tid, int lane, int warp_m, int warp_n,
    float c[4][4][4])
{
    const int a_row = warp_m * 64 + (lane & 15);
    const int sA = (a_row >> 1) & 3;                     // swizzle key (mf*16 invariant)
    const int b_row = warp_n * 32 + ((lane >> 4) << 3) + (lane & 7);
    const int sB = (b_row >> 1) & 3;                     // p*16 invariant
    const int ca = (lane >> 4);          // 0..1
    const int cb = ((lane >> 3) & 1);    // 0..1

    load_chunk_g(sbase, 0, Ah, Al, Bh, Bl, bm, bn, 0,  tid);
    load_chunk_g(sbase, 1, Ah, Al, Bh, Bl, bm, bn, 32, tid);

    const int NCHUNK = DD / 32;
    for (int i = 0; i < NCHUNK; ++i) {
        const int st = i % 3;
        if (i < NCHUNK - 1) asm volatile("cp.async.wait_group 1;" ::: "memory");
        else                asm volatile("cp.async.wait_group 0;" ::: "memory");
        __syncthreads();
        if (i + 2 < NCHUNK)
            load_chunk_g(sbase, (i + 2) % 3, Ah, Al, Bh, Bl, bm, bn, (i + 2) * 32, tid);

        const uint32_t stb = sbase + st * STAGE;
        #pragma unroll
        for (int ks = 0; ks < 2; ++ks) {
            uint32_t ah[4][4], al[4][4], bh[2][4], bl[2][4];
            const uint32_t ac = (uint32_t)(((ks * 2 + ca) ^ sA) << 4);
            const uint32_t bc = (uint32_t)(((ks * 2 + cb) ^ sB) << 4);
            #pragma unroll
            for (int mf = 0; mf < 4; ++mf) {
                uint32_t ra = stb + T_AH + (uint32_t)((a_row + mf * 16) * 64) + ac;
                LDM_X4(ah[mf], ra);
                LDM_X4(al[mf], ra + (T_AL - T_AH));
            }
            #pragma unroll
            for (int p = 0; p < 2; ++p) {
                uint32_t rb = stb + T_BH + (uint32_t)((b_row + p * 16) * 64) + bc;
                LDM_X4(bh[p], rb);
                LDM_X4(bl[p], rb + (T_BL - T_BH));
            }
            #pragma unroll
            for (int mf = 0; mf < 4; ++mf)
                #pragma unroll
                for (int nf = 0; nf < 4; ++nf) {
                    const int p = nf >> 1, hh = (nf & 1) * 2;
                    MMA_BF16(c[mf][nf], ah[mf], bh[p][hh], bh[p][hh+1]);
                    MMA_BF16(c[mf][nf], ah[mf], bl[p][hh], bl[p][hh+1]);
                    MMA_BF16(c[mf][nf], al[mf], bh[p][hh], bh[p][hh+1]);
                }
        }
    }
}

__global__ __launch_bounds__(256, 2) void qkv_gemm(
    const __nv_bfloat16* __restrict__ Ahi_all, const __nv_bfloat16* __restrict__ Alo_all,
    const __nv_bfloat16* __restrict__ Whi_all, const __nv_bfloat16* __restrict__ Wlo_all,
    const float* __restrict__ bq, const float* __restrict__ bk, const float* __restrict__ bv,
    __nv_bfloat16* __restrict__ Qhi, __nv_bfloat16* __restrict__ Qlo,
    __nv_bfloat16* __restrict__ Khi, __nv_bfloat16* __restrict__ Klo,
    __half* __restrict__ Vh)
{
    extern __shared__ char smem[];
    const uint32_t sbase = smem_u32(smem);
    const int tid = threadIdx.x, wid = tid >> 5, lane = tid & 31;
    const int warp_m = wid & 1, warp_n = wid >> 1;
    const int proj = blockIdx.x >> 3;
    const int bn = (blockIdx.x & 7) * 128;
    const int bm = blockIdx.y * 128;

    const __nv_bfloat16* Ah = Ahi_all + (size_t)proj * MTOT * DD;
    const __nv_bfloat16* Al = Alo_all + (size_t)proj * MTOT * DD;
    const __nv_bfloat16* Bh = Whi_all + (size_t)proj * DD * DD;
    const __nv_bfloat16* Bl = Wlo_all + (size_t)proj * DD * DD;
    const float* bias = (proj == 0) ? bq : (proj == 1) ? bk : bv;

    float c[4][4][4];
    #pragma unroll
    for (int i = 0; i < 4; ++i)
        #pragma unroll
        for (int j = 0; j < 4; ++j)
            #pragma unroll
            for (int e = 0; e < 4; ++e) c[i][j][e] = 0.f;

    gemm_core(sbase, Ah, Al, Bh, Bl, bm, bn, tid, lane, warp_m, warp_n, c);

    __nv_bfloat16* Oh = (proj == 0) ? Qhi : Khi;
    __nv_bfloat16* Ol = (proj == 0) ? Qlo : Klo;

    #pragma unroll
    for (int mf = 0; mf < 4; ++mf) {
        int m0 = bm + warp_m * 64 + mf * 16 + (lane >> 2);
        #pragma unroll
        for (int nf = 0; nf < 4; ++nf) {
            int n = bn + warp_n * 32 + nf * 8 + (lane & 3) * 2;
            float2 bb = *(const float2*)&bias[n];
            float v0 = c[mf][nf][0] + bb.x, v1 = c[mf][nf][1] + bb.y;
            float v2 = c[mf][nf][2] + bb.x, v3 = c[mf][nf][3] + bb.y;
            size_t i0 = (size_t)m0 * DD + n, i1 = (size_t)(m0 + 8) * DD + n;
            if (proj == 2) {
                *(__half2*)&Vh[i0] = __floats2half2_rn(v0, v1);
                *(__half2*)&Vh[i1] = __floats2half2_rn(v2, v3);
            } else {
                __nv_bfloat16 h0 = __float2bfloat16_rn(v0), h1 = __float2bfloat16_rn(v1);
                __nv_bfloat16 h2 = __float2bfloat16_rn(v2), h3 = __float2bfloat16_rn(v3);
                __nv_bfloat162 H0; H0.x = h0; H0.y = h1;
                __nv_bfloat162 H1; H1.x = h2; H1.y = h3;
                __nv_bfloat162 L0, L1;
                L0.x = __float2bfloat16_rn(v0 - __bfloat162float(h0));
                L0.y = __float2bfloat16_rn(v1 - __bfloat162float(h1));
                L1.x = __float2bfloat16_rn(v2 - __bfloat162float(h2));
                L1.y = __float2bfloat16_rn(v3 - __bfloat162float(h3));
                *(__nv_bfloat162*)&Oh[i0] = H0; *(__nv_bfloat162*)&Oh[i1] = H1;
                *(__nv_bfloat162*)&Ol[i0] = L0; *(__nv_bfloat162*)&Ol[i1] = L1;
            }
        }
    }
}

__global__ __launch_bounds__(256, 2) void out_gemm(
    const __nv_bfloat16* __restrict__ Ah, const __nv_bfloat16* __restrict__ Al,
    const __nv_bfloat16* __restrict__ Bh, const __nv_bfloat16* __restrict__ Bl,
    const float* __restrict__ bias, float* __restrict__ C)
{
    extern __shared__ char smem[];
    const uint32_t sbase = smem_u32(smem);
    const int tid = threadIdx.x, wid = tid >> 5, lane = tid & 31;
    const int warp_m = wid & 1, warp_n = wid >> 1;
    const int bm = blockIdx.y * 128, bn = blockIdx.x * 128;

    float c[4][4][4];
    #pragma unroll
    for (int i = 0; i < 4; ++i)
        #pragma unroll
        for (int j = 0; j < 4; ++j)
            #pragma unroll
            for (int e = 0; e < 4; ++e) c[i][j][e] = 0.f;

    gemm_core(sbase, Ah, Al, Bh, Bl, bm, bn, tid, lane, warp_m, warp_n, c);

    #pragma unroll
    for (int mf = 0; mf < 4; ++mf) {
        int m0 = bm + warp_m * 64 + mf * 16 + (lane >> 2);
        #pragma unroll
        for (int nf = 0; nf < 4; ++nf) {
            int n = bn + warp_n * 32 + nf * 8 + (lane & 3) * 2;
            float2 bb = *(const float2*)&bias[n];
            *(float2*)&C[(size_t)m0 * DD + n] =
                make_float2(c[mf][nf][0] + bb.x, c[mf][nf][1] + bb.y);
            *(float2*)&C[(size_t)(m0 + 8) * DD + n] =
                make_float2(c[mf][nf][2] + bb.x, c[mf][nf][3] + bb.y);
        }
    }
}

// ============ flash attention: 3-stage KV, occ 2, SW128 swizzle ============
// rows are 128B (= 64 head dims); unit swizzle c ^= row&7
#define S_QH 0
#define S_QL 16384
#define S_KV(st) (32768 + (st)*24576)
#define KO_H 0
#define KO_L 8192
#define KO_V 16384
#define ATTN_SMEM (32768 + 3*24576)   // 106496

__device__ __forceinline__ void load_kv(uint32_t sb, int st,
    const char* Khb, const char* Klb, const char* Vhb, int key0, int tid)
{
    uint32_t base = sb + S_KV(st);
    #pragma unroll
    for (int p = 0; p < 2; ++p) {
        int id = tid + p * 256;            // 0..511
        int row = id >> 3, c = id & 7;
        int cs = c ^ (row & 7);
        size_t go = (size_t)(key0 + row) * (DD * 2) + c * 16;
        uint32_t so = (uint32_t)(row * 128 + cs * 16);
        cp_async16(base + KO_H + so, Khb + go);
        cp_async16(base + KO_L + so, Klb + go);
        cp_async16(base + KO_V + so, Vhb + go);
    }
    CP_COMMIT();
}

__global__ __launch_bounds__(256, 2) void attn_kernel(
    const __nv_bfloat16* __restrict__ Qh, const __nv_bfloat16* __restrict__ Ql,
    const __nv_bfloat16* __restrict__ Kh, const __nv_bfloat16* __restrict__ Kl,
    const __half* __restrict__ Vv,
    __nv_bfloat16* __restrict__ Xhi, __nv_bfloat16* __restrict__ Xlo)
{
    extern __shared__ char sm[];
    const uint32_t sb = smem_u32(sm);
    const int tid = threadIdx.x, lane = tid & 31, w = tid >> 5;
    const int q0 = blockIdx.x * 128;
    const int b = blockIdx.y >> 4, h = blockIdx.y & 15;
    const int g = lane >> 2, qr = lane & 3;
    const int wrow = w * 16;

    const char* Qhb = (const char*)(Qh + (size_t)b * SS * DD + h * 64);
    const char* Qlb = (const char*)(Ql + (size_t)b * SS * DD + h * 64);
    const char* Khb = (const char*)(Kh + (size_t)b * SS * DD + h * 64);
    const char* Klb = (const char*)(Kl + (size_t)b * SS * DD + h * 64);
    const char* Vhb = (const char*)(Vv + (size_t)b * SS * DD + h * 64);

    // Q tiles (hi/lo): 128 rows x 128B, swizzled
    #pragma unroll
    for (int p = 0; p < 4; ++p) {
        int id = tid + p * 256;            // 0..1023
        int row = id >> 3, c = id & 7;
        int cs = c ^ (row & 7);
        size_t go = (size_t)(q0 + row) * (DD * 2) + c * 16;
        uint32_t so = (uint32_t)(row * 128 + cs * 16);
        cp_async16(sb + S_QH + so, Qhb + go);
        cp_async16(sb + S_QL + so, Qlb + go);
    }
    CP_COMMIT();
    load_kv(sb, 0, Khb, Klb, Vhb, 0, tid);
    load_kv(sb, 1, Khb, Klb, Vhb, 64, tid);

    // hoist Q fragments (wait for Q group only)
    asm volatile("cp.async.wait_group 2;" ::: "memory");
    __syncthreads();
    const int q_row = wrow + (lane & 15);
    const int kq = q_row & 7;
    const int ca = lane >> 4;              // 0..1
    uint32_t qh[4][4], ql[4][4];
    #pragma unroll
    for (int kc = 0; kc < 4; ++kc) {
        uint32_t ra = sb + S_QH + (uint32_t)(q_row * 128 + (((kc * 2 + ca) ^ kq) << 4));
        LDM_X4(qh[kc], ra);
        LDM_X4(ql[kc], ra + (S_QL - S_QH));
    }

    const int k_rowb = ((lane >> 4) << 3) + (lane & 7);
    const int kk = lane & 7;               // swizzle key for K rows (p*16 invariant)
    const int cb = (lane >> 3) & 1;
    const int v_row = (((lane >> 3) & 1) << 3) + (lane & 7);   // within 16-row group
    const int kv_key = lane & 7;
    const int cv = lane >> 4;

    float m0 = -1e30f, m1 = -1e30f, l0 = 0.f, l1 = 0.f;
    float o[8][4];
    #pragma unroll
    for (int j = 0; j < 8; ++j)
        #pragma unroll
        for (int e = 0; e < 4; ++e) o[j][e] = 0.f;

    const int NK = SS / 64;
    for (int kt = 0; kt < NK; ++kt) {
        const int st = kt % 3;
        if (kt < NK - 1) asm volatile("cp.async.wait_group 1;" ::: "memory");
        else             asm volatile("cp.async.wait_group 0;" ::: "memory");
        __syncthreads();
        if (kt + 2 < NK)
            load_kv(sb, (kt + 2) % 3, Khb, Klb, Vhb, (kt + 2) * 64, tid);

        const uint32_t KVb = sb + S_KV(st);

        // ---- S = Q K^T (split bf16) ----
        float s[8][4];
        #pragma unroll
        for (int j = 0; j < 8; ++j)
            #pragma unroll
            for (int e = 0; e < 4; ++e) s[j][e] = 0.f;

        #pragma unroll
        for (int kc = 0; kc < 4; ++kc) {
            const uint32_t kcol = (uint32_t)((((kc * 2 + cb) ^ kk) << 4));
            #pragma unroll
            for (int p = 0; p < 4; ++p) {
                uint32_t rb = KVb + KO_H + (uint32_t)((k_rowb + p * 16) * 128) + kcol;
                uint32_t kh4[4], kl4[4];
                LDM_X4(kh4, rb);
                LDM_X4(kl4, rb + (KO_L - KO_H));
                MMA_BF16(s[2*p],   qh[kc], kh4[0], kh4[1]);
                MMA_BF16(s[2*p],   qh[kc], kl4[0], kl4[1]);
                MMA_BF16(s[2*p],   ql[kc], kh4[0], kh4[1]);
                MMA_BF16(s[2*p+1], qh[kc], kh4[2], kh4[3]);
                MMA_BF16(s[2*p+1], qh[kc], kl4[2], kl4[3]);
                MMA_BF16(s[2*p+1], ql[kc], kh4[2], kh4[3]);
            }
        }

        // ---- online softmax (l kept per-lane; only max reduced) ----
        float mx0 = -1e30f, mx1 = -1e30f;
        #pragma unroll
        for (int j = 0; j < 8; ++j) {
            mx0 = fmaxf(mx0, fmaxf(s[j][0], s[j][1]));
            mx1 = fmaxf(mx1, fmaxf(s[j][2], s[j][3]));
        }
        mx0 = fmaxf(mx0, __shfl_xor_sync(0xffffffffu, mx0, 1));
        mx0 = fmaxf(mx0, __shfl_xor_sync(0xffffffffu, mx0, 2));
        mx1 = fmaxf(mx1, __shfl_xor_sync(0xffffffffu, mx1, 1));
        mx1 = fmaxf(mx1, __shfl_xor_sync(0xffffffffu, mx1, 2));
        float m0n = fmaxf(m0, mx0), m1n = fmaxf(m1, mx1);
        float sc0 = __expf(m0 - m0n), sc1 = __expf(m1 - m1n);
        float ps0 = 0.f, ps1 = 0.f;
        #pragma unroll
        for (int j = 0; j < 8; ++j) {
            s[j][0] = __expf(s[j][0] - m0n);
            s[j][1] = __expf(s[j][1] - m0n);
            s[j][2] = __expf(s[j][2] - m1n);
            s[j][3] = __expf(s[j][3] - m1n);
            ps0 += s[j][0] + s[j][1];
            ps1 += s[j][2] + s[j][3];
            o[j][0] *= sc0; o[j][1] *= sc0;
            o[j][2] *= sc1; o[j][3] *= sc1;
        }
        l0 = l0 * sc0 + ps0;
        l1 = l1 * sc1 + ps1;
        m0 = m0n; m1 = m1n;

        // ---- O += P V (fp16, trans ldmatrix with swizzle) ----
        const uint32_t vbase = KVb + KO_V;
        #pragma unroll
        for (int kc = 0; kc < 4; ++kc) {
            const int j0 = 2 * kc, j1 = 2 * kc + 1;
            uint32_t a0 = f2h2(s[j0][0], s[j0][1]);
            uint32_t a1 = f2h2(s[j0][2], s[j0][3]);
            uint32_t a2 = f2h2(s[j1][0], s[j1][1]);
            uint32_t a3 = f2h2(s[j1][2], s[j1][3]);
            const int mrow = kc * 16 + v_row;
            #pragma unroll
            for (int nfp = 0; nfp < 4; ++nfp) {
                const int nf = 2 * nfp;
                uint32_t addr = vbase + (uint32_t)(mrow * 128
                                 + (((nf + cv) ^ kv_key) << 4));
                uint32_t r0, r1, r2, r3;
                asm volatile("ldmatrix.sync.aligned.m8n8.x4.trans.shared.b16 {%0,%1,%2,%3}, [%4];"
                    : "=r"(r0), "=r"(r1), "=r"(r2), "=r"(r3) : "r"(addr));
                MMA_F16(o[nf],     a0, a1, a2, a3, r0, r1);
                MMA_F16(o[nf + 1], a0, a1, a2, a3, r2, r3);
            }
        }
    }

    // lane-reduce l (deferred from loop)
    l0 += __shfl_xor_sync(0xffffffffu, l0, 1);
    l0 += __shfl_xor_sync(0xffffffffu, l0, 2);
    l1 += __shfl_xor_sync(0xffffffffu, l1, 1);
    l1 += __shfl_xor_sync(0xffffffffu, l1, 2);

    float inv0 = 1.0f / l0, inv1 = 1.0f / l1;
    size_t r0g = ((size_t)(h * BB + b) * SS + q0 + wrow + g) * 64;
    size_t r1g = r0g + 8 * 64;
    #pragma unroll
    for (int nf = 0; nf < 8; ++nf) {
        int col = nf * 8 + qr * 2;
        float v0 = o[nf][0] * inv0, v1 = o[nf][1] * inv0;
        float v2 = o[nf][2] * inv1, v3 = o[nf][3] * inv1;
        __nv_bfloat16 h0 = __float2bfloat16_rn(v0), h1 = __float2bfloat16_rn(v1);
        __nv_bfloat16 h2 = __float2bfloat16_rn(v2), h3 = __float2bfloat16_rn(v3);
        __nv_bfloat162 H0; H0.x = h0; H0.y = h1;
        __nv_bfloat162 H1; H1.x = h2; H1.y = h3;
        __nv_bfloat162 L0, L1;
        L0.x = __float2bfloat16_rn(v0 - __bfloat162float(h0));
        L0.y = __float2bfloat16_rn(v1 - __bfloat162float(h1));
        L1.x = __float2bfloat16_rn(v2 - __bfloat162float(h2));
        L1.y = __float2bfloat16_rn(v3 - __bfloat162float(h3));
        *(__nv_bfloat162*)&Xhi[r0g + col] = H0;
        *(__nv_bfloat162*)&Xhi[r1g + col] = H1;
        *(__nv_bfloat162*)&Xlo[r0g + col] = L0;
        *(__nv_bfloat162*)&Xlo[r1g + col] = L1;
    }
}

extern "C" void kernel_launch(void* const* d_in, const int* in_sizes, int n_in,
                              void* d_out, int out_size)
{
    const float* q  = (const float*)d_in[0];
    const float* k  = (const float*)d_in[1];
    const float* v  = (const float*)d_in[2];
    const float* wq = (const float*)d_in[3];
    const float* bq = (const float*)d_in[4];
    const float* wk = (const float*)d_in[5];
    const float* bk = (const float*)d_in[6];
    const float* wv = (const float*)d_in[7];
    const float* bv = (const float*)d_in[8];
    const float* wo = (const float*)d_in[9];
    const float* bo = (const float*)d_in[10];
    float* out = (float*)d_out;

    __nv_bfloat16 *Whi, *Wlo, *Ahi, *Alo, *Qhi, *Qlo, *Khi, *Klo, *Xhi, *Xlo;
    __half *Vh;
    cudaGetSymbolAddress((void**)&Whi, g_Whi);
    cudaGetSymbolAddress((void**)&Wlo, g_Wlo);
    cudaGetSymbolAddress((void**)&Ahi, g_Ahi);
    cudaGetSymbolAddress((void**)&Alo, g_Alo);
    cudaGetSymbolAddress((void**)&Qhi, g_Qhi);
    cudaGetSymbolAddress((void**)&Qlo, g_Qlo);
    cudaGetSymbolAddress((void**)&Khi, g_Khi);
    cudaGetSymbolAddress((void**)&Klo, g_Klo);
    cudaGetSymbolAddress((void**)&Xhi, g_Xhi);
    cudaGetSymbolAddress((void**)&Xlo, g_Xlo);
    cudaGetSymbolAddress((void**)&Vh,  g_Vh);

    cudaFuncSetAttribute(qkv_gemm,    cudaFuncAttributeMaxDynamicSharedMemorySize, GEMM_SMEM);
    cudaFuncSetAttribute(out_gemm,    cudaFuncAttributeMaxDynamicSharedMemorySize, GEMM_SMEM);
    cudaFuncSetAttribute(attn_kernel, cudaFuncAttributeMaxDynamicSharedMemorySize, ATTN_SMEM);

    dim3 tGrid(DD / 32, DD / 32, 4), tBlk(32, 8);
    trans_split_kernel<<<tGrid, tBlk>>>(wq, wk, wv, wo, Whi, Wlo);

    const int n4 = MTOT * DD / 4;
    dim3 sGrid((n4 + 255) / 256, 1, 3);
    split_kernel<<<sGrid, 256>>>(q, k, v, Ahi, Alo, n4);

    dim3 qkvGrid(24, MTOT / 128);
    qkv_gemm<<<qkvGrid, 256, GEMM_SMEM>>>(Ahi, Alo, Whi, Wlo, bq, bk, bv,
                                          Qhi, Qlo, Khi, Klo, Vh);

    dim3 aGrid(SS / 128, BB * HH);
    attn_kernel<<<aGrid, 256, ATTN_SMEM>>>(Qhi, Qlo, Khi, Klo, Vh, Xhi, Xlo);

    dim3 oGrid(DD / 128, MTOT / 128);
    out_gemm<<<oGrid, 256, GEMM_SMEM>>>(Xhi, Xlo, Whi + 3*(size_t)DD*DD, Wlo + 3*(size_t)DD*DD,
                                        bo, out);
}

// round 9
// speedup vs baseline: 3.0254x; 1.0337x over previous
#include <cuda_runtime.h>
#include <cuda_bf16.h>
#include <cuda_fp16.h>
#include <cstdint>
#include <math.h>

#define BB 2
#define SS 2048
#define DD 1024
#define HH 16
#define DHH 64
#define MTOT (BB*SS)
#define LOG2E 1.44269504088896f

__device__ __align__(256) __nv_bfloat16 g_Whi[4][DD*DD];
__device__ __align__(256) __nv_bfloat16 g_Wlo[4][DD*DD];
__device__ __align__(256) __nv_bfloat16 g_Ahi[3][MTOT*DD];
__device__ __align__(256) __nv_bfloat16 g_Alo[3][MTOT*DD];
__device__ __align__(256) __nv_bfloat16 g_Qhi[MTOT*DD];
__device__ __align__(256) __nv_bfloat16 g_Qlo[MTOT*DD];
__device__ __align__(256) __nv_bfloat16 g_Khi[MTOT*DD];
__device__ __align__(256) __nv_bfloat16 g_Klo[MTOT*DD];
__device__ __align__(256) __half        g_Vh [MTOT*DD];
__device__ __align__(256) __nv_bfloat16 g_Xhi[MTOT*DD];
__device__ __align__(256) __nv_bfloat16 g_Xlo[MTOT*DD];

__device__ __forceinline__ uint32_t smem_u32(const void* p) {
    uint32_t a;
    asm("{ .reg .u64 t; cvta.to.shared.u64 t, %1; cvt.u32.u64 %0, t; }" : "=r"(a) : "l"(p));
    return a;
}
__device__ __forceinline__ void cp_async16(uint32_t dst, const void* src) {
    asm volatile("cp.async.cg.shared.global [%0], [%1], 16;" :: "r"(dst), "l"(src));
}
#define CP_COMMIT() asm volatile("cp.async.commit_group;" ::: "memory")

#define MMA_BF16(c, a, b0, b1) \
    asm volatile("mma.sync.aligned.m16n8k16.row.col.f32.bf16.bf16.f32 " \
        "{%0,%1,%2,%3}, {%4,%5,%6,%7}, {%8,%9}, {%0,%1,%2,%3};" \
        : "+f"((c)[0]), "+f"((c)[1]), "+f"((c)[2]), "+f"((c)[3]) \
        : "r"((a)[0]), "r"((a)[1]), "r"((a)[2]), "r"((a)[3]), "r"(b0), "r"(b1))

#define MMA_F16(c, a0, a1, a2, a3, b0, b1) \
    asm volatile("mma.sync.aligned.m16n8k16.row.col.f32.f16.f16.f32 " \
        "{%0,%1,%2,%3}, {%4,%5,%6,%7}, {%8,%9}, {%0,%1,%2,%3};" \
        : "+f"((c)[0]), "+f"((c)[1]), "+f"((c)[2]), "+f"((c)[3]) \
        : "r"(a0), "r"(a1), "r"(a2), "r"(a3), "r"(b0), "r"(b1))

#define LDM_X4(r, a) \
    asm volatile("ldmatrix.sync.aligned.m8n8.x4.shared.b16 {%0,%1,%2,%3}, [%4];" \
        : "=r"((r)[0]), "=r"((r)[1]), "=r"((r)[2]), "=r"((r)[3]) : "r"(a))

__device__ __forceinline__ uint32_t f2h2(float x, float y) {
    __half2 t = __floats2half2_rn(x, y);
    return *(uint32_t*)&t;
}
__device__ __forceinline__ float ex2(float x) {
    float y;
    asm("ex2.approx.ftz.f32 %0, %1;" : "=f"(y) : "f"(x));
    return y;
}

// ============ fused weight transpose + split ============
__global__ __launch_bounds__(256) void trans_split_kernel(
    const float* __restrict__ w0, const float* __restrict__ w1,
    const float* __restrict__ w2, const float* __restrict__ w3,
    __nv_bfloat16* __restrict__ hi_base, __nv_bfloat16* __restrict__ lo_base)
{
    const float* in = (blockIdx.z == 0) ? w0 : (blockIdx.z == 1) ? w1
                     : (blockIdx.z == 2) ? w2 : w3;
    __nv_bfloat16* hi = hi_base + (size_t)blockIdx.z * DD * DD;
    __nv_bfloat16* lo = lo_base + (size_t)blockIdx.z * DD * DD;
    __shared__ float t[32][33];
    int x = blockIdx.x * 32 + threadIdx.x;
    int y = blockIdx.y * 32 + threadIdx.y;
    #pragma unroll
    for (int j = 0; j < 32; j += 8)
        t[threadIdx.y + j][threadIdx.x] = in[(size_t)(y + j) * DD + x];
    __syncthreads();
    int x2 = blockIdx.y * 32 + threadIdx.x;
    int y2 = blockIdx.x * 32 + threadIdx.y;
    #pragma unroll
    for (int j = 0; j < 32; j += 8) {
        float w = t[threadIdx.x][threadIdx.y + j];
        __nv_bfloat16 h = __float2bfloat16_rn(w);
        hi[(size_t)(y2 + j) * DD + x2] = h;
        lo[(size_t)(y2 + j) * DD + x2] = __float2bfloat16_rn(w - __bfloat162float(h));
    }
}

// ============ fused activation split ============
__global__ __launch_bounds__(256) void split_kernel(
    const float* __restrict__ a0, const float* __restrict__ a1,
    const float* __restrict__ a2,
    __nv_bfloat16* __restrict__ hi_base, __nv_bfloat16* __restrict__ lo_base, int n4)
{
    int i = blockIdx.x * blockDim.x + threadIdx.x;
    if (i >= n4) return;
    const float* a = (blockIdx.z == 0) ? a0 : (blockIdx.z == 1) ? a1 : a2;
    __nv_bfloat16* hi = hi_base + (size_t)blockIdx.z * MTOT * DD;
    __nv_bfloat16* lo = lo_base + (size_t)blockIdx.z * MTOT * DD;
    float4 v = ((const float4*)a)[i];
    __nv_bfloat16 hx = __float2bfloat16_rn(v.x), hy = __float2bfloat16_rn(v.y);
    __nv_bfloat16 hz = __float2bfloat16_rn(v.z), hw = __float2bfloat16_rn(v.w);
    __nv_bfloat162 h0; h0.x = hx; h0.y = hy;
    __nv_bfloat162 h1; h1.x = hz; h1.y = hw;
    __nv_bfloat162 l0, l1;
    l0.x = __float2bfloat16_rn(v.x - __bfloat162float(hx));
    l0.y = __float2bfloat16_rn(v.y - __bfloat162float(hy));
    l1.x = __float2bfloat16_rn(v.z - __bfloat162float(hz));
    l1.y = __float2bfloat16_rn(v.w - __bfloat162float(hw));
    ((__nv_bfloat162*)hi)[i*2+0] = h0; ((__nv_bfloat162*)hi)[i*2+1] = h1;
    ((__nv_bfloat162*)lo)[i*2+0] = l0; ((__nv_bfloat162*)lo)[i*2+1] = l1;
}

// ============ split-bf16 GEMM: 3-stage, occ 2, swizzled 64B rows ============
#define T_AH    0
#define T_AL    8192
#define T_BH    16384
#define T_BL    24576
#define STAGE   32768
#define GEMM_SMEM (3*STAGE)

__device__ __forceinline__ void load_chunk_g(
    uint32_t sbase, int st,
    const __nv_bfloat16* __restrict__ Ah, const __nv_bfloat16* __restrict__ Al,
    const __nv_bfloat16* __restrict__ Bh, const __nv_bfloat16* __restrict__ Bl,
    int bm, int bn, int k0, int tid)
{
    uint32_t s = sbase + st * STAGE;
    #pragma unroll
    for (int it = 0; it < 2; ++it) {
        int idx = tid + it * 256;
        int row = idx >> 2, q = idx & 3;
        int qs = q ^ ((row >> 1) & 3);
        uint32_t doff = (uint32_t)(row * 64 + qs * 16);
        size_t ga = (size_t)(bm + row) * DD + k0 + q * 8;
        size_t gb = (size_t)(bn + row) * DD + k0 + q * 8;
        cp_async16(s + T_AH + doff, Ah + ga);
        cp_async16(s + T_AL + doff, Al + ga);
        cp_async16(s + T_BH + doff, Bh + gb);
        cp_async16(s + T_BL + doff, Bl + gb);
    }
    CP_COMMIT();
}

__device__ __forceinline__ void gemm_core(
    uint32_t sbase, const __nv_bfloat16* Ah, const __nv_bfloat16* Al,
    const __nv_bfloat16* Bh, const __nv_bfloat16* Bl,
    int bm, int bn, int tid, int lane, int warp_m, int warp_n,
    float c[4][4][4])
{
    const int a_row = warp_m * 64 + (lane & 15);
    const int sA = (a_row >> 1) & 3;
    const int b_row = warp_n * 32 + ((lane >> 4) << 3) + (lane & 7);
    const int sB = (b_row >> 1) & 3;
    const int ca = (lane >> 4);
    const int cb = ((lane >> 3) & 1);

    load_chunk_g(sbase, 0, Ah, Al, Bh, Bl, bm, bn, 0,  tid);
    load_chunk_g(sbase, 1, Ah, Al, Bh, Bl, bm, bn, 32, tid);

    const int NCHUNK = DD / 32;
    for (int i = 0; i < NCHUNK; ++i) {
        const int st = i % 3;
        if (i < NCHUNK - 1) asm volatile("cp.async.wait_group 1;" ::: "memory");
        else                asm volatile("cp.async.wait_group 0;" ::: "memory");
        __syncthreads();
        if (i + 2 < NCHUNK)
            load_chunk_g(sbase, (i + 2) % 3, Ah, Al, Bh, Bl, bm, bn, (i + 2) * 32, tid);

        const uint32_t stb = sbase + st * STAGE;
        #pragma unroll
        for (int ks = 0; ks < 2; ++ks) {
            uint32_t ah[4][4], al[4][4], bh[2][4], bl[2][4];
            const uint32_t ac = (uint32_t)(((ks * 2 + ca) ^ sA) << 4);
            const uint32_t bc = (uint32_t)(((ks * 2 + cb) ^ sB) << 4);
            #pragma unroll
            for (int mf = 0; mf < 4; ++mf) {
                uint32_t ra = stb + T_AH + (uint32_t)((a_row + mf * 16) * 64) + ac;
                LDM_X4(ah[mf], ra);
                LDM_X4(al[mf], ra + (T_AL - T_AH));
            }
            #pragma unroll
            for (int p = 0; p < 2; ++p) {
                uint32_t rb = stb + T_BH + (uint32_t)((b_row + p * 16) * 64) + bc;
                LDM_X4(bh[p], rb);
                LDM_X4(bl[p], rb + (T_BL - T_BH));
            }
            #pragma unroll
            for (int mf = 0; mf < 4; ++mf)
                #pragma unroll
                for (int nf = 0; nf < 4; ++nf) {
                    const int p = nf >> 1, hh = (nf & 1) * 2;
                    MMA_BF16(c[mf][nf], ah[mf], bh[p][hh], bh[p][hh+1]);
                    MMA_BF16(c[mf][nf], ah[mf], bl[p][hh], bl[p][hh+1]);
                    MMA_BF16(c[mf][nf], al[mf], bh[p][hh], bh[p][hh+1]);
                }
        }
    }
}

__global__ __launch_bounds__(256, 2) void qkv_gemm(
    const __nv_bfloat16* __restrict__ Ahi_all, const __nv_bfloat16* __restrict__ Alo_all,
    const __nv_bfloat16* __restrict__ Whi_all, const __nv_bfloat16* __restrict__ Wlo_all,
    const float* __restrict__ bq, const float* __restrict__ bk, const float* __restrict__ bv,
    __nv_bfloat16* __restrict__ Qhi, __nv_bfloat16* __restrict__ Qlo,
    __nv_bfloat16* __restrict__ Khi, __nv_bfloat16* __restrict__ Klo,
    __half* __restrict__ Vh)
{
    extern __shared__ char smem[];
    const uint32_t sbase = smem_u32(smem);
    const int tid = threadIdx.x, wid = tid >> 5, lane = tid & 31;
    const int warp_m = wid & 1, warp_n = wid >> 1;
    const int proj = blockIdx.x >> 3;
    const int bn = (blockIdx.x & 7) * 128;
    const int bm = blockIdx.y * 128;

    const __nv_bfloat16* Ah = Ahi_all + (size_t)proj * MTOT * DD;
    const __nv_bfloat16* Al = Alo_all + (size_t)proj * MTOT * DD;
    const __nv_bfloat16* Bh = Whi_all + (size_t)proj * DD * DD;
    const __nv_bfloat16* Bl = Wlo_all + (size_t)proj * DD * DD;
    const float* bias = (proj == 0) ? bq : (proj == 1) ? bk : bv;
    // Q is pre-scaled by log2(e) so attention scores live in the exp2 domain
    const float oscale = (proj == 0) ? LOG2E : 1.0f;

    float c[4][4][4];
    #pragma unroll
    for (int i = 0; i < 4; ++i)
        #pragma unroll
        for (int j = 0; j < 4; ++j)
            #pragma unroll
            for (int e = 0; e < 4; ++e) c[i][j][e] = 0.f;

    gemm_core(sbase, Ah, Al, Bh, Bl, bm, bn, tid, lane, warp_m, warp_n, c);

    __nv_bfloat16* Oh = (proj == 0) ? Qhi : Khi;
    __nv_bfloat16* Ol = (proj == 0) ? Qlo : Klo;

    #pragma unroll
    for (int mf = 0; mf < 4; ++mf) {
        int m0 = bm + warp_m * 64 + mf * 16 + (lane >> 2);
        #pragma unroll
        for (int nf = 0; nf < 4; ++nf) {
            int n = bn + warp_n * 32 + nf * 8 + (lane & 3) * 2;
            float2 bb = *(const float2*)&bias[n];
            float v0 = (c[mf][nf][0] + bb.x) * oscale, v1 = (c[mf][nf][1] + bb.y) * oscale;
            float v2 = (c[mf][nf][2] + bb.x) * oscale, v3 = (c[mf][nf][3] + bb.y) * oscale;
            size_t i0 = (size_t)m0 * DD + n, i1 = (size_t)(m0 + 8) * DD + n;
            if (proj == 2) {
                *(__half2*)&Vh[i0] = __floats2half2_rn(v0, v1);
                *(__half2*)&Vh[i1] = __floats2half2_rn(v2, v3);
            } else {
                __nv_bfloat16 h0 = __float2bfloat16_rn(v0), h1 = __float2bfloat16_rn(v1);
                __nv_bfloat16 h2 = __float2bfloat16_rn(v2), h3 = __float2bfloat16_rn(v3);
                __nv_bfloat162 H0; H0.x = h0; H0.y = h1;
                __nv_bfloat162 H1; H1.x = h2; H1.y = h3;
                __nv_bfloat162 L0, L1;
                L0.x = __float2bfloat16_rn(v0 - __bfloat162float(h0));
                L0.y = __float2bfloat16_rn(v1 - __bfloat162float(h1));
                L1.x = __float2bfloat16_rn(v2 - __bfloat162float(h2));
                L1.y = __float2bfloat16_rn(v3 - __bfloat162float(h3));
                *(__nv_bfloat162*)&Oh[i0] = H0; *(__nv_bfloat162*)&Oh[i1] = H1;
                *(__nv_bfloat162*)&Ol[i0] = L0; *(__nv_bfloat162*)&Ol[i1] = L1;
            }
        }
    }
}

__global__ __launch_bounds__(256, 2) void out_gemm(
    const __nv_bfloat16* __restrict__ Ah, const __nv_bfloat16* __restrict__ Al,
    const __nv_bfloat16* __restrict__ Bh, const __nv_bfloat16* __restrict__ Bl,
    const float* __restrict__ bias, float* __restrict__ C)
{
    extern __shared__ char smem[];
    const uint32_t sbase = smem_u32(smem);
    const int tid = threadIdx.x, wid = tid >> 5, lane = tid & 31;
    const int warp_m = wid & 1, warp_n = wid >> 1;
    const int bm = blockIdx.y * 128, bn = blockIdx.x * 128;

    float c[4][4][4];
    #pragma unroll
    for (int i = 0; i < 4; ++i)
        #pragma unroll
        for (int j = 0; j < 4; ++j)
            #pragma unroll
            for (int e = 0; e < 4; ++e) c[i][j][e] = 0.f;

    gemm_core(sbase, Ah, Al, Bh, Bl, bm, bn, tid, lane, warp_m, warp_n, c);

    #pragma unroll
    for (int mf = 0; mf < 4; ++mf) {
        int m0 = bm + warp_m * 64 + mf * 16 + (lane >> 2);
        #pragma unroll
        for (int nf = 0; nf < 4; ++nf) {
            int n = bn + warp_n * 32 + nf * 8 + (lane & 3) * 2;
            float2 bb = *(const float2*)&bias[n];
            *(float2*)&C[(size_t)m0 * DD + n] =
                make_float2(c[mf][nf][0] + bb.x, c[mf][nf][1] + bb.y);
            *(float2*)&C[(size_t)(m0 + 8) * DD + n] =
                make_float2(c[mf][nf][2] + bb.x, c[mf][nf][3] + bb.y);
        }
    }
}

// ============ flash attention: 3-stage KV, occ 2, interleaved softmax/PV ============
#define S_QH 0
#define S_QL 16384
#define S_KV(st) (32768 + (st)*24576)
#define KO_H 0
#define KO_L 8192
#define KO_V 16384
#define ATTN_SMEM (32768 + 3*24576)

__device__ __forceinline__ void load_kv(uint32_t sb, int st,
    const char* Khb, const char* Klb, const char* Vhb, int key0, int tid)
{
    uint32_t base = sb + S_KV(st);
    #pragma unroll
    for (int p = 0; p < 2; ++p) {
        int id = tid + p * 256;
        int row = id >> 3, c = id & 7;
        int cs = c ^ (row & 7);
        size_t go = (size_t)(key0 + row) * (DD * 2) + c * 16;
        uint32_t so = (uint32_t)(row * 128 + cs * 16);
        cp_async16(base + KO_H + so, Khb + go);
        cp_async16(base + KO_L + so, Klb + go);
        cp_async16(base + KO_V + so, Vhb + go);
    }
    CP_COMMIT();
}

__global__ __launch_bounds__(256, 2) void attn_kernel(
    const __nv_bfloat16* __restrict__ Qh, const __nv_bfloat16* __restrict__ Ql,
    const __nv_bfloat16* __restrict__ Kh, const __nv_bfloat16* __restrict__ Kl,
    const __half* __restrict__ Vv,
    __nv_bfloat16* __restrict__ Xhi, __nv_bfloat16* __restrict__ Xlo)
{
    extern __shared__ char sm[];
    const uint32_t sb = smem_u32(sm);
    const int tid = threadIdx.x, lane = tid & 31, w = tid >> 5;
    const int q0 = blockIdx.x * 128;
    const int b = blockIdx.y >> 4, h = blockIdx.y & 15;
    const int g = lane >> 2, qr = lane & 3;
    const int wrow = w * 16;

    const char* Qhb = (const char*)(Qh + (size_t)b * SS * DD + h * 64);
    const char* Qlb = (const char*)(Ql + (size_t)b * SS * DD + h * 64);
    const char* Khb = (const char*)(Kh + (size_t)b * SS * DD + h * 64);
    const char* Klb = (const char*)(Kl + (size_t)b * SS * DD + h * 64);
    const char* Vhb = (const char*)(Vv + (size_t)b * SS * DD + h * 64);

    #pragma unroll
    for (int p = 0; p < 4; ++p) {
        int id = tid + p * 256;
        int row = id >> 3, c = id & 7;
        int cs = c ^ (row & 7);
        size_t go = (size_t)(q0 + row) * (DD * 2) + c * 16;
        uint32_t so = (uint32_t)(row * 128 + cs * 16);
        cp_async16(sb + S_QH + so, Qhb + go);
        cp_async16(sb + S_QL + so, Qlb + go);
    }
    CP_COMMIT();
    load_kv(sb, 0, Khb, Klb, Vhb, 0, tid);
    load_kv(sb, 1, Khb, Klb, Vhb, 64, tid);

    asm volatile("cp.async.wait_group 2;" ::: "memory");
    __syncthreads();
    const int q_row = wrow + (lane & 15);
    const int kq = q_row & 7;
    const int ca = lane >> 4;
    uint32_t qh[4][4], ql[4][4];
    #pragma unroll
    for (int kc = 0; kc < 4; ++kc) {
        uint32_t ra = sb + S_QH + (uint32_t)(q_row * 128 + (((kc * 2 + ca) ^ kq) << 4));
        LDM_X4(qh[kc], ra);
        LDM_X4(ql[kc], ra + (S_QL - S_QH));
    }

    const int k_rowb = ((lane >> 4) << 3) + (lane & 7);
    const int kk = lane & 7;
    const int cb = (lane >> 3) & 1;
    const int v_row = (((lane >> 3) & 1) << 3) + (lane & 7);
    const int kv_key = lane & 7;
    const int cv = lane >> 4;

    float m0 = -1e30f, m1 = -1e30f, l0 = 0.f, l1 = 0.f;
    float o[8][4];
    #pragma unroll
    for (int j = 0; j < 8; ++j)
        #pragma unroll
        for (int e = 0; e < 4; ++e) o[j][e] = 0.f;

    const int NK = SS / 64;
    for (int kt = 0; kt < NK; ++kt) {
        const int st = kt % 3;
        if (kt < NK - 1) asm volatile("cp.async.wait_group 1;" ::: "memory");
        else             asm volatile("cp.async.wait_group 0;" ::: "memory");
        __syncthreads();
        if (kt + 2 < NK)
            load_kv(sb, (kt + 2) % 3, Khb, Klb, Vhb, (kt + 2) * 64, tid);

        const uint32_t KVb = sb + S_KV(st);

        // ---- S = Q K^T (split bf16; scores already in log2 domain) ----
        float s[8][4];
        #pragma unroll
        for (int j = 0; j < 8; ++j)
            #pragma unroll
            for (int e = 0; e < 4; ++e) s[j][e] = 0.f;

        #pragma unroll
        for (int kc = 0; kc < 4; ++kc) {
            const uint32_t kcol = (uint32_t)((((kc * 2 + cb) ^ kk) << 4));
            #pragma unroll
            for (int p = 0; p < 4; ++p) {
                uint32_t rb = KVb + KO_H + (uint32_t)((k_rowb + p * 16) * 128) + kcol;
                uint32_t kh4[4], kl4[4];
                LDM_X4(kh4, rb);
                LDM_X4(kl4, rb + (KO_L - KO_H));
                MMA_BF16(s[2*p],   qh[kc], kh4[0], kh4[1]);
                MMA_BF16(s[2*p],   qh[kc], kl4[0], kl4[1]);
                MMA_BF16(s[2*p],   ql[kc], kh4[0], kh4[1]);
                MMA_BF16(s[2*p+1], qh[kc], kh4[2], kh4[3]);
                MMA_BF16(s[2*p+1], qh[kc], kl4[2], kl4[3]);
                MMA_BF16(s[2*p+1], ql[kc], kh4[2], kh4[3]);
            }
        }

        // ---- max + conditional rescale ----
        float mx0 = -1e30f, mx1 = -1e30f;
        #pragma unroll
        for (int j = 0; j < 8; ++j) {
            mx0 = fmaxf(mx0, fmaxf(s[j][0], s[j][1]));
            mx1 = fmaxf(mx1, fmaxf(s[j][2], s[j][3]));
        }
        mx0 = fmaxf(mx0, __shfl_xor_sync(0xffffffffu, mx0, 1));
        mx0 = fmaxf(mx0, __shfl_xor_sync(0xffffffffu, mx0, 2));
        mx1 = fmaxf(mx1, __shfl_xor_sync(0xffffffffu, mx1, 1));
        mx1 = fmaxf(mx1, __shfl_xor_sync(0xffffffffu, mx1, 2));
        float m0n = fmaxf(m0, mx0), m1n = fmaxf(m1, mx1);
        bool nore = __all_sync(0xffffffffu, (m0n == m0) && (m1n == m1));
        if (!nore) {
            float sc0 = ex2(m0 - m0n), sc1 = ex2(m1 - m1n);
            l0 *= sc0; l1 *= sc1;
            #pragma unroll
            for (int j = 0; j < 8; ++j) {
                o[j][0] *= sc0; o[j][1] *= sc0;
                o[j][2] *= sc1; o[j][3] *= sc1;
            }
        }
        m0 = m0n; m1 = m1n;

        // ---- interleaved exp + PV per kc (softmax hides under tensor) ----
        const uint32_t vbase = KVb + KO_V;
        #pragma unroll
        for (int kc = 0; kc < 4; ++kc) {
            const int j0 = 2 * kc, j1 = 2 * kc + 1;
            float e00 = ex2(s[j0][0] - m0n), e01 = ex2(s[j0][1] - m0n);
            float e02 = ex2(s[j0][2] - m1n), e03 = ex2(s[j0][3] - m1n);
            float e10 = ex2(s[j1][0] - m0n), e11 = ex2(s[j1][1] - m0n);
            float e12 = ex2(s[j1][2] - m1n), e13 = ex2(s[j1][3] - m1n);
            l0 += e00 + e01 + e10 + e11;
            l1 += e02 + e03 + e12 + e13;
            uint32_t a0 = f2h2(e00, e01);
            uint32_t a1 = f2h2(e02, e03);
            uint32_t a2 = f2h2(e10, e11);
            uint32_t a3 = f2h2(e12, e13);
            const int mrow = kc * 16 + v_row;
            #pragma unroll
            for (int nfp = 0; nfp < 4; ++nfp) {
                const int nf = 2 * nfp;
                uint32_t addr = vbase + (uint32_t)(mrow * 128
                                 + (((nf + cv) ^ kv_key) << 4));
                uint32_t r0, r1, r2, r3;
                asm volatile("ldmatrix.sync.aligned.m8n8.x4.trans.shared.b16 {%0,%1,%2,%3}, [%4];"
                    : "=r"(r0), "=r"(r1), "=r"(r2), "=r"(r3) : "r"(addr));
                MMA_F16(o[nf],     a0, a1, a2, a3, r0, r1);
                MMA_F16(o[nf + 1], a0, a1, a2, a3, r2, r3);
            }
        }
    }

    l0 += __shfl_xor_sync(0xffffffffu, l0, 1);
    l0 += __shfl_xor_sync(0xffffffffu, l0, 2);
    l1 += __shfl_xor_sync(0xffffffffu, l1, 1);
    l1 += __shfl_xor_sync(0xffffffffu, l1, 2);

    float inv0 = 1.0f / l0, inv1 = 1.0f / l1;
    size_t r0g = ((size_t)(h * BB + b) * SS + q0 + wrow + g) * 64;
    size_t r1g = r0g + 8 * 64;
    #pragma unroll
    for (int nf = 0; nf < 8; ++nf) {
        int col = nf * 8 + qr * 2;
        float v0 = o[nf][0] * inv0, v1 = o[nf][1] * inv0;
        float v2 = o[nf][2] * inv1, v3 = o[nf][3] * inv1;
        __nv_bfloat16 h0 = __float2bfloat16_rn(v0), h1 = __float2bfloat16_rn(v1);
        __nv_bfloat16 h2 = __float2bfloat16_rn(v2), h3 = __float2bfloat16_rn(v3);
        __nv_bfloat162 H0; H0.x = h0; H0.y = h1;
        __nv_bfloat162 H1; H1.x = h2; H1.y = h3;
        __nv_bfloat162 L0, L1;
        L0.x = __float2bfloat16_rn(v0 - __bfloat162float(h0));
        L0.y = __float2bfloat16_rn(v1 - __bfloat162float(h1));
        L1.x = __float2bfloat16_rn(v2 - __bfloat162float(h2));
        L1.y = __float2bfloat16_rn(v3 - __bfloat162float(h3));
        *(__nv_bfloat162*)&Xhi[r0g + col] = H0;
        *(__nv_bfloat162*)&Xhi[r1g + col] = H1;
        *(__nv_bfloat162*)&Xlo[r0g + col] = L0;
        *(__nv_bfloat162*)&Xlo[r1g + col] = L1;
    }
}

extern "C" void kernel_launch(void* const* d_in, const int* in_sizes, int n_in,
                              void* d_out, int out_size)
{
    const float* q  = (const float*)d_in[0];
    const float* k  = (const float*)d_in[1];
    const float* v  = (const float*)d_in[2];
    const float* wq = (const float*)d_in[3];
    const float* bq = (const float*)d_in[4];
    const float* wk = (const float*)d_in[5];
    const float* bk = (const float*)d_in[6];
    const float* wv = (const float*)d_in[7];
    const float* bv = (const float*)d_in[8];
    const float* wo = (const float*)d_in[9];
    const float* bo = (const float*)d_in[10];
    float* out = (float*)d_out;

    __nv_bfloat16 *Whi, *Wlo, *Ahi, *Alo, *Qhi, *Qlo, *Khi, *Klo, *Xhi, *Xlo;
    __half *Vh;
    cudaGetSymbolAddress((void**)&Whi, g_Whi);
    cudaGetSymbolAddress((void**)&Wlo, g_Wlo);
    cudaGetSymbolAddress((void**)&Ahi, g_Ahi);
    cudaGetSymbolAddress((void**)&Alo, g_Alo);
    cudaGetSymbolAddress((void**)&Qhi, g_Qhi);
    cudaGetSymbolAddress((void**)&Qlo, g_Qlo);
    cudaGetSymbolAddress((void**)&Khi, g_Khi);
    cudaGetSymbolAddress((void**)&Klo, g_Klo);
    cudaGetSymbolAddress((void**)&Xhi, g_Xhi);
    cudaGetSymbolAddress((void**)&Xlo, g_Xlo);
    cudaGetSymbolAddress((void**)&Vh,  g_Vh);

    cudaFuncSetAttribute(qkv_gemm,    cudaFuncAttributeMaxDynamicSharedMemorySize, GEMM_SMEM);
    cudaFuncSetAttribute(out_gemm,    cudaFuncAttributeMaxDynamicSharedMemorySize, GEMM_SMEM);
    cudaFuncSetAttribute(attn_kernel, cudaFuncAttributeMaxDynamicSharedMemorySize, ATTN_SMEM);

    dim3 tGrid(DD / 32, DD / 32, 4), tBlk(32, 8);
    trans_split_kernel<<<tGrid, tBlk>>>(wq, wk, wv, wo, Whi, Wlo);

    const int n4 = MTOT * DD / 4;
    dim3 sGrid((n4 + 255) / 256, 1, 3);
    split_kernel<<<sGrid, 256>>>(q, k, v, Ahi, Alo, n4);

    dim3 qkvGrid(24, MTOT / 128);
    qkv_gemm<<<qkvGrid, 256, GEMM_SMEM>>>(Ahi, Alo, Whi, Wlo, bq, bk, bv,
                                          Qhi, Qlo, Khi, Klo, Vh);

    dim3 aGrid(SS / 128, BB * HH);
    attn_kernel<<<aGrid, 256, ATTN_SMEM>>>(Qhi, Qlo, Khi, Klo, Vh, Xhi, Xlo);

    dim3 oGrid(DD / 128, MTOT / 128);
    out_gemm<<<oGrid, 256, GEMM_SMEM>>>(Xhi, Xlo, Whi + 3*(size_t)DD*DD, Wlo + 3*(size_t)DD*DD,
                                        bo, out);
}

// round 10
// speedup vs baseline: 3.0355x; 1.0033x over previous
#include <cuda_runtime.h>
#include <cuda_bf16.h>
#include <cuda_fp16.h>
#include <cstdint>
#include <math.h>

#define BB 2
#define SS 2048
#define DD 1024
#define HH 16
#define DHH 64
#define MTOT (BB*SS)
#define LOG2E 1.44269504088896f

__device__ __align__(256) __nv_bfloat16 g_Whi[4][DD*DD];
__device__ __align__(256) __nv_bfloat16 g_Wlo[4][DD*DD];
__device__ __align__(256) __nv_bfloat16 g_Ahi[3][MTOT*DD];
__device__ __align__(256) __nv_bfloat16 g_Alo[3][MTOT*DD];
__device__ __align__(256) __nv_bfloat16 g_Qhi[MTOT*DD];
__device__ __align__(256) __nv_bfloat16 g_Qlo[MTOT*DD];
__device__ __align__(256) __nv_bfloat16 g_Khi[MTOT*DD];
__device__ __align__(256) __nv_bfloat16 g_Klo[MTOT*DD];
__device__ __align__(256) __half        g_Vh [MTOT*DD];
__device__ __align__(256) __nv_bfloat16 g_Xhi[MTOT*DD];
__device__ __align__(256) __nv_bfloat16 g_Xlo[MTOT*DD];

__device__ __forceinline__ uint32_t smem_u32(const void* p) {
    uint32_t a;
    asm("{ .reg .u64 t; cvta.to.shared.u64 t, %1; cvt.u32.u64 %0, t; }" : "=r"(a) : "l"(p));
    return a;
}
__device__ __forceinline__ void cp_async16(uint32_t dst, const void* src) {
    asm volatile("cp.async.cg.shared.global [%0], [%1], 16;" :: "r"(dst), "l"(src));
}
#define CP_COMMIT() asm volatile("cp.async.commit_group;" ::: "memory")

#define MMA_BF16(c, a, b0, b1) \
    asm volatile("mma.sync.aligned.m16n8k16.row.col.f32.bf16.bf16.f32 " \
        "{%0,%1,%2,%3}, {%4,%5,%6,%7}, {%8,%9}, {%0,%1,%2,%3};" \
        : "+f"((c)[0]), "+f"((c)[1]), "+f"((c)[2]), "+f"((c)[3]) \
        : "r"((a)[0]), "r"((a)[1]), "r"((a)[2]), "r"((a)[3]), "r"(b0), "r"(b1))

#define MMA_F16(c, a0, a1, a2, a3, b0, b1) \
    asm volatile("mma.sync.aligned.m16n8k16.row.col.f32.f16.f16.f32 " \
        "{%0,%1,%2,%3}, {%4,%5,%6,%7}, {%8,%9}, {%0,%1,%2,%3};" \
        : "+f"((c)[0]), "+f"((c)[1]), "+f"((c)[2]), "+f"((c)[3]) \
        : "r"(a0), "r"(a1), "r"(a2), "r"(a3), "r"(b0), "r"(b1))

#define LDM_X4(r, a) \
    asm volatile("ldmatrix.sync.aligned.m8n8.x4.shared.b16 {%0,%1,%2,%3}, [%4];" \
        : "=r"((r)[0]), "=r"((r)[1]), "=r"((r)[2]), "=r"((r)[3]) : "r"(a))

__device__ __forceinline__ uint32_t f2h2(float x, float y) {
    __half2 t = __floats2half2_rn(x, y);
    return *(uint32_t*)&t;
}
__device__ __forceinline__ float ex2(float x) {
    float y;
    asm("ex2.approx.ftz.f32 %0, %1;" : "=f"(y) : "f"(x));
    return y;
}

// ============ fused weight transpose + split ============
__global__ __launch_bounds__(256) void trans_split_kernel(
    const float* __restrict__ w0, const float* __restrict__ w1,
    const float* __restrict__ w2, const float* __restrict__ w3,
    __nv_bfloat16* __restrict__ hi_base, __nv_bfloat16* __restrict__ lo_base)
{
    const float* in = (blockIdx.z == 0) ? w0 : (blockIdx.z == 1) ? w1
                     : (blockIdx.z == 2) ? w2 : w3;
    __nv_bfloat16* hi = hi_base + (size_t)blockIdx.z * DD * DD;
    __nv_bfloat16* lo = lo_base + (size_t)blockIdx.z * DD * DD;
    __shared__ float t[32][33];
    int x = blockIdx.x * 32 + threadIdx.x;
    int y = blockIdx.y * 32 + threadIdx.y;
    #pragma unroll
    for (int j = 0; j < 32; j += 8)
        t[threadIdx.y + j][threadIdx.x] = in[(size_t)(y + j) * DD + x];
    __syncthreads();
    int x2 = blockIdx.y * 32 + threadIdx.x;
    int y2 = blockIdx.x * 32 + threadIdx.y;
    #pragma unroll
    for (int j = 0; j < 32; j += 8) {
        float w = t[threadIdx.x][threadIdx.y + j];
        __nv_bfloat16 h = __float2bfloat16_rn(w);
        hi[(size_t)(y2 + j) * DD + x2] = h;
        lo[(size_t)(y2 + j) * DD + x2] = __float2bfloat16_rn(w - __bfloat162float(h));
    }
}

// ============ fused activation split ============
__global__ __launch_bounds__(256) void split_kernel(
    const float* __restrict__ a0, const float* __restrict__ a1,
    const float* __restrict__ a2,
    __nv_bfloat16* __restrict__ hi_base, __nv_bfloat16* __restrict__ lo_base, int n4)
{
    int i = blockIdx.x * blockDim.x + threadIdx.x;
    if (i >= n4) return;
    const float* a = (blockIdx.z == 0) ? a0 : (blockIdx.z == 1) ? a1 : a2;
    __nv_bfloat16* hi = hi_base + (size_t)blockIdx.z * MTOT * DD;
    __nv_bfloat16* lo = lo_base + (size_t)blockIdx.z * MTOT * DD;
    float4 v = ((const float4*)a)[i];
    __nv_bfloat16 hx = __float2bfloat16_rn(v.x), hy = __float2bfloat16_rn(v.y);
    __nv_bfloat16 hz = __float2bfloat16_rn(v.z), hw = __float2bfloat16_rn(v.w);
    __nv_bfloat162 h0; h0.x = hx; h0.y = hy;
    __nv_bfloat162 h1; h1.x = hz; h1.y = hw;
    __nv_bfloat162 l0, l1;
    l0.x = __float2bfloat16_rn(v.x - __bfloat162float(hx));
    l0.y = __float2bfloat16_rn(v.y - __bfloat162float(hy));
    l1.x = __float2bfloat16_rn(v.z - __bfloat162float(hz));
    l1.y = __float2bfloat16_rn(v.w - __bfloat162float(hw));
    ((__nv_bfloat162*)hi)[i*2+0] = h0; ((__nv_bfloat162*)hi)[i*2+1] = h1;
    ((__nv_bfloat162*)lo)[i*2+0] = l0; ((__nv_bfloat162*)lo)[i*2+1] = l1;
}

// ============ split-bf16 GEMM: 3-stage, occ 2, swizzled 64B rows ============
#define T_AH    0
#define T_AL    8192
#define T_BH    16384
#define T_BL    24576
#define STAGE   32768
#define GEMM_SMEM (3*STAGE)

__device__ __forceinline__ void load_chunk_g(
    uint32_t sbase, int st,
    const __nv_bfloat16* __restrict__ Ah, const __nv_bfloat16* __restrict__ Al,
    const __nv_bfloat16* __restrict__ Bh, const __nv_bfloat16* __restrict__ Bl,
    int bm, int bn, int k0, int tid)
{
    uint32_t s = sbase + st * STAGE;
    #pragma unroll
    for (int it = 0; it < 2; ++it) {
        int idx = tid + it * 256;
        int row = idx >> 2, q = idx & 3;
        int qs = q ^ ((row >> 1) & 3);
        uint32_t doff = (uint32_t)(row * 64 + qs * 16);
        size_t ga = (size_t)(bm + row) * DD + k0 + q * 8;
        size_t gb = (size_t)(bn + row) * DD + k0 + q * 8;
        cp_async16(s + T_AH + doff, Ah + ga);
        cp_async16(s + T_AL + doff, Al + ga);
        cp_async16(s + T_BH + doff, Bh + gb);
        cp_async16(s + T_BL + doff, Bl + gb);
    }
    CP_COMMIT();
}

__device__ __forceinline__ void gemm_core(
    uint32_t sbase, const __nv_bfloat16* Ah, const __nv_bfloat16* Al,
    const __nv_bfloat16* Bh, const __nv_bfloat16* Bl,
    int bm, int bn, int tid, int lane, int warp_m, int warp_n,
    float c[4][4][4])
{
    const int a_row = warp_m * 64 + (lane & 15);
    const int sA = (a_row >> 1) & 3;
    const int b_row = warp_n * 32 + ((lane >> 4) << 3) + (lane & 7);
    const int sB = (b_row >> 1) & 3;
    const int ca = (lane >> 4);
    const int cb = ((lane >> 3) & 1);

    load_chunk_g(sbase, 0, Ah, Al, Bh, Bl, bm, bn, 0,  tid);
    load_chunk_g(sbase, 1, Ah, Al, Bh, Bl, bm, bn, 32, tid);

    const int NCHUNK = DD / 32;
    for (int i = 0; i < NCHUNK; ++i) {
        const int st = i % 3;
        if (i < NCHUNK - 1) asm volatile("cp.async.wait_group 1;" ::: "memory");
        else                asm volatile("cp.async.wait_group 0;" ::: "memory");
        __syncthreads();
        if (i + 2 < NCHUNK)
            load_chunk_g(sbase, (i + 2) % 3, Ah, Al, Bh, Bl, bm, bn, (i + 2) * 32, tid);

        const uint32_t stb = sbase + st * STAGE;
        #pragma unroll
        for (int ks = 0; ks < 2; ++ks) {
            uint32_t ah[4][4], al[4][4], bh[2][4], bl[2][4];
            const uint32_t ac = (uint32_t)(((ks * 2 + ca) ^ sA) << 4);
            const uint32_t bc = (uint32_t)(((ks * 2 + cb) ^ sB) << 4);
            #pragma unroll
            for (int mf = 0; mf < 4; ++mf) {
                uint32_t ra = stb + T_AH + (uint32_t)((a_row + mf * 16) * 64) + ac;
                LDM_X4(ah[mf], ra);
                LDM_X4(al[mf], ra + (T_AL - T_AH));
            }
            #pragma unroll
            for (int p = 0; p < 2; ++p) {
                uint32_t rb = stb + T_BH + (uint32_t)((b_row + p * 16) * 64) + bc;
                LDM_X4(bh[p], rb);
                LDM_X4(bl[p], rb + (T_BL - T_BH));
            }
            #pragma unroll
            for (int mf = 0; mf < 4; ++mf)
                #pragma unroll
                for (int nf = 0; nf < 4; ++nf) {
                    const int p = nf >> 1, hh = (nf & 1) * 2;
                    MMA_BF16(c[mf][nf], ah[mf], bh[p][hh], bh[p][hh+1]);
                    MMA_BF16(c[mf][nf], ah[mf], bl[p][hh], bl[p][hh+1]);
                    MMA_BF16(c[mf][nf], al[mf], bh[p][hh], bh[p][hh+1]);
                }
        }
    }
}

__global__ __launch_bounds__(256, 2) void qkv_gemm(
    const __nv_bfloat16* __restrict__ Ahi_all, const __nv_bfloat16* __restrict__ Alo_all,
    const __nv_bfloat16* __restrict__ Whi_all, const __nv_bfloat16* __restrict__ Wlo_all,
    const float* __restrict__ bq, const float* __restrict__ bk, const float* __restrict__ bv,
    __nv_bfloat16* __restrict__ Qhi, __nv_bfloat16* __restrict__ Qlo,
    __nv_bfloat16* __restrict__ Khi, __nv_bfloat16* __restrict__ Klo,
    __half* __restrict__ Vh)
{
    extern __shared__ char smem[];
    const uint32_t sbase = smem_u32(smem);
    const int tid = threadIdx.x, wid = tid >> 5, lane = tid & 31;
    const int warp_m = wid & 1, warp_n = wid >> 1;
    const int proj = blockIdx.x >> 3;
    const int bn = (blockIdx.x & 7) * 128;
    const int bm = blockIdx.y * 128;

    const __nv_bfloat16* Ah = Ahi_all + (size_t)proj * MTOT * DD;
    const __nv_bfloat16* Al = Alo_all + (size_t)proj * MTOT * DD;
    const __nv_bfloat16* Bh = Whi_all + (size_t)proj * DD * DD;
    const __nv_bfloat16* Bl = Wlo_all + (size_t)proj * DD * DD;
    const float* bias = (proj == 0) ? bq : (proj == 1) ? bk : bv;
    const float oscale = (proj == 0) ? LOG2E : 1.0f;

    float c[4][4][4];
    #pragma unroll
    for (int i = 0; i < 4; ++i)
        #pragma unroll
        for (int j = 0; j < 4; ++j)
            #pragma unroll
            for (int e = 0; e < 4; ++e) c[i][j][e] = 0.f;

    gemm_core(sbase, Ah, Al, Bh, Bl, bm, bn, tid, lane, warp_m, warp_n, c);

    __nv_bfloat16* Oh = (proj == 0) ? Qhi : Khi;
    __nv_bfloat16* Ol = (proj == 0) ? Qlo : Klo;

    #pragma unroll
    for (int mf = 0; mf < 4; ++mf) {
        int m0 = bm + warp_m * 64 + mf * 16 + (lane >> 2);
        #pragma unroll
        for (int nf = 0; nf < 4; ++nf) {
            int n = bn + warp_n * 32 + nf * 8 + (lane & 3) * 2;
            float2 bb = *(const float2*)&bias[n];
            float v0 = (c[mf][nf][0] + bb.x) * oscale, v1 = (c[mf][nf][1] + bb.y) * oscale;
            float v2 = (c[mf][nf][2] + bb.x) * oscale, v3 = (c[mf][nf][3] + bb.y) * oscale;
            size_t i0 = (size_t)m0 * DD + n, i1 = (size_t)(m0 + 8) * DD + n;
            if (proj == 2) {
                *(__half2*)&Vh[i0] = __floats2half2_rn(v0, v1);
                *(__half2*)&Vh[i1] = __floats2half2_rn(v2, v3);
            } else {
                __nv_bfloat16 h0 = __float2bfloat16_rn(v0), h1 = __float2bfloat16_rn(v1);
                __nv_bfloat16 h2 = __float2bfloat16_rn(v2), h3 = __float2bfloat16_rn(v3);
                __nv_bfloat162 H0; H0.x = h0; H0.y = h1;
                __nv_bfloat162 H1; H1.x = h2; H1.y = h3;
                __nv_bfloat162 L0, L1;
                L0.x = __float2bfloat16_rn(v0 - __bfloat162float(h0));
                L0.y = __float2bfloat16_rn(v1 - __bfloat162float(h1));
                L1.x = __float2bfloat16_rn(v2 - __bfloat162float(h2));
                L1.y = __float2bfloat16_rn(v3 - __bfloat162float(h3));
                *(__nv_bfloat162*)&Oh[i0] = H0; *(__nv_bfloat162*)&Oh[i1] = H1;
                *(__nv_bfloat162*)&Ol[i0] = L0; *(__nv_bfloat162*)&Ol[i1] = L1;
            }
        }
    }
}

__global__ __launch_bounds__(256, 2) void out_gemm(
    const __nv_bfloat16* __restrict__ Ah, const __nv_bfloat16* __restrict__ Al,
    const __nv_bfloat16* __restrict__ Bh, const __nv_bfloat16* __restrict__ Bl,
    const float* __restrict__ bias, float* __restrict__ C)
{
    extern __shared__ char smem[];
    const uint32_t sbase = smem_u32(smem);
    const int tid = threadIdx.x, wid = tid >> 5, lane = tid & 31;
    const int warp_m = wid & 1, warp_n = wid >> 1;
    const int bm = blockIdx.y * 128, bn = blockIdx.x * 128;

    float c[4][4][4];
    #pragma unroll
    for (int i = 0; i < 4; ++i)
        #pragma unroll
        for (int j = 0; j < 4; ++j)
            #pragma unroll
            for (int e = 0; e < 4; ++e) c[i][j][e] = 0.f;

    gemm_core(sbase, Ah, Al, Bh, Bl, bm, bn, tid, lane, warp_m, warp_n, c);

    #pragma unroll
    for (int mf = 0; mf < 4; ++mf) {
        int m0 = bm + warp_m * 64 + mf * 16 + (lane >> 2);
        #pragma unroll
        for (int nf = 0; nf < 4; ++nf) {
            int n = bn + warp_n * 32 + nf * 8 + (lane & 3) * 2;
            float2 bb = *(const float2*)&bias[n];
            *(float2*)&C[(size_t)m0 * DD + n] =
                make_float2(c[mf][nf][0] + bb.x, c[mf][nf][1] + bb.y);
            *(float2*)&C[(size_t)(m0 + 8) * DD + n] =
                make_float2(c[mf][nf][2] + bb.x, c[mf][nf][3] + bb.y);
        }
    }
}

// ============ flash attention: 2-stage 128-key KV ring (stage0 overlays Q) ============
// Stage layout (48KB): KH [0,16K), KL [16K,32K), V [32K,48K); 128 rows x 128B, c^=row&7
#define AKH 0
#define AKL 16384
#define AKV 32768
#define AST 49152
#define ATTN_SMEM (2*AST)   // 98304

__device__ __forceinline__ void load_kv128(uint32_t stage_base,
    const char* Khb, const char* Klb, const char* Vhb, int key0, int tid)
{
    #pragma unroll
    for (int p = 0; p < 4; ++p) {
        int id = tid + p * 256;            // 0..1023
        int row = id >> 3, c = id & 7;
        int cs = c ^ (row & 7);
        size_t go = (size_t)(key0 + row) * (DD * 2) + c * 16;
        uint32_t so = (uint32_t)(row * 128 + cs * 16);
        cp_async16(stage_base + AKH + so, Khb + go);
        cp_async16(stage_base + AKL + so, Klb + go);
        cp_async16(stage_base + AKV + so, Vhb + go);
    }
    CP_COMMIT();
}

__global__ __launch_bounds__(256, 2) void attn_kernel(
    const __nv_bfloat16* __restrict__ Qh, const __nv_bfloat16* __restrict__ Ql,
    const __nv_bfloat16* __restrict__ Kh, const __nv_bfloat16* __restrict__ Kl,
    const __half* __restrict__ Vv,
    __nv_bfloat16* __restrict__ Xhi, __nv_bfloat16* __restrict__ Xlo)
{
    extern __shared__ char sm[];
    const uint32_t sb = smem_u32(sm);
    const int tid = threadIdx.x, lane = tid & 31, w = tid >> 5;
    const int q0 = blockIdx.x * 128;
    const int b = blockIdx.y >> 4, h = blockIdx.y & 15;
    const int g = lane >> 2, qr = lane & 3;
    const int wrow = w * 16;

    const char* Qhb = (const char*)(Qh + (size_t)b * SS * DD + h * 64);
    const char* Qlb = (const char*)(Ql + (size_t)b * SS * DD + h * 64);
    const char* Khb = (const char*)(Kh + (size_t)b * SS * DD + h * 64);
    const char* Klb = (const char*)(Kl + (size_t)b * SS * DD + h * 64);
    const char* Vhb = (const char*)(Vv + (size_t)b * SS * DD + h * 64);

    // Q tiles (hi at sb+0, lo at sb+16K) — this area becomes stage 0 after hoist
    #pragma unroll
    for (int p = 0; p < 4; ++p) {
        int id = tid + p * 256;
        int row = id >> 3, c = id & 7;
        int cs = c ^ (row & 7);
        size_t go = (size_t)(q0 + row) * (DD * 2) + c * 16;
        uint32_t so = (uint32_t)(row * 128 + cs * 16);
        cp_async16(sb + 0 + so, Qhb + go);
        cp_async16(sb + 16384 + so, Qlb + go);
    }
    CP_COMMIT();

    // hoist Q fragments, then release the Q region for KV stage 0
    asm volatile("cp.async.wait_group 0;" ::: "memory");
    __syncthreads();
    const int q_row = wrow + (lane & 15);
    const int kq = q_row & 7;
    const int ca = lane >> 4;
    uint32_t qh[4][4], ql[4][4];
    #pragma unroll
    for (int kc = 0; kc < 4; ++kc) {
        uint32_t ra = sb + (uint32_t)(q_row * 128 + (((kc * 2 + ca) ^ kq) << 4));
        LDM_X4(qh[kc], ra);
        LDM_X4(ql[kc], ra + 16384);
    }
    __syncthreads();                       // all warps hoisted before stage0 overwrite
    load_kv128(sb, Khb, Klb, Vhb, 0, tid); // KV tile 0 -> stage 0 (overlays Q)

    const int k_rowb = ((lane >> 4) << 3) + (lane & 7);
    const int kk = lane & 7;
    const int cb = (lane >> 3) & 1;
    const int v_row = (((lane >> 3) & 1) << 3) + (lane & 7);
    const int kv_key = lane & 7;
    const int cv = lane >> 4;

    float m0 = -1e30f, m1 = -1e30f, l0 = 0.f, l1 = 0.f;
    float o[8][4];
    #pragma unroll
    for (int j = 0; j < 8; ++j)
        #pragma unroll
        for (int e = 0; e < 4; ++e) o[j][e] = 0.f;

    const int NK = SS / 128;   // 16 stages of 128 keys
    for (int kt = 0; kt < NK; ++kt) {
        asm volatile("cp.async.wait_group 0;" ::: "memory");   // stage kt data ready
        __syncthreads();                                        // all warps done with kt-1
        if (kt + 1 < NK)
            load_kv128(sb + (uint32_t)(((kt + 1) & 1) * AST),
                       Khb, Klb, Vhb, (kt + 1) * 128, tid);

        const uint32_t STb = sb + (uint32_t)((kt & 1) * AST);

        #pragma unroll
        for (int half = 0; half < 2; ++half) {
            const int rbase = half * 64;

            // ---- S = Q K^T (split bf16; log2-domain scores) ----
            float s[8][4];
            #pragma unroll
            for (int j = 0; j < 8; ++j)
                #pragma unroll
                for (int e = 0; e < 4; ++e) s[j][e] = 0.f;

            #pragma unroll
            for (int kc = 0; kc < 4; ++kc) {
                const uint32_t kcol = (uint32_t)((((kc * 2 + cb) ^ kk) << 4));
                #pragma unroll
                for (int p = 0; p < 4; ++p) {
                    uint32_t rb = STb + AKH
                        + (uint32_t)((rbase + k_rowb + p * 16) * 128) + kcol;
                    uint32_t kh4[4], kl4[4];
                    LDM_X4(kh4, rb);
                    LDM_X4(kl4, rb + (AKL - AKH));
                    MMA_BF16(s[2*p],   qh[kc], kh4[0], kh4[1]);
                    MMA_BF16(s[2*p],   qh[kc], kl4[0], kl4[1]);
                    MMA_BF16(s[2*p],   ql[kc], kh4[0], kh4[1]);
                    MMA_BF16(s[2*p+1], qh[kc], kh4[2], kh4[3]);
                    MMA_BF16(s[2*p+1], qh[kc], kl4[2], kl4[3]);
                    MMA_BF16(s[2*p+1], ql[kc], kh4[2], kh4[3]);
                }
            }

            // ---- max + conditional rescale ----
            float mx0 = -1e30f, mx1 = -1e30f;
            #pragma unroll
            for (int j = 0; j < 8; ++j) {
                mx0 = fmaxf(mx0, fmaxf(s[j][0], s[j][1]));
                mx1 = fmaxf(mx1, fmaxf(s[j][2], s[j][3]));
            }
            mx0 = fmaxf(mx0, __shfl_xor_sync(0xffffffffu, mx0, 1));
            mx0 = fmaxf(mx0, __shfl_xor_sync(0xffffffffu, mx0, 2));
            mx1 = fmaxf(mx1, __shfl_xor_sync(0xffffffffu, mx1, 1));
            mx1 = fmaxf(mx1, __shfl_xor_sync(0xffffffffu, mx1, 2));
            float m0n = fmaxf(m0, mx0), m1n = fmaxf(m1, mx1);
            bool nore = __all_sync(0xffffffffu, (m0n == m0) && (m1n == m1));
            if (!nore) {
                float sc0 = ex2(m0 - m0n), sc1 = ex2(m1 - m1n);
                l0 *= sc0; l1 *= sc1;
                #pragma unroll
                for (int j = 0; j < 8; ++j) {
                    o[j][0] *= sc0; o[j][1] *= sc0;
                    o[j][2] *= sc1; o[j][3] *= sc1;
                }
            }
            m0 = m0n; m1 = m1n;

            // ---- interleaved exp + PV per kc ----
            const uint32_t vbase = STb + AKV;
            #pragma unroll
            for (int kc = 0; kc < 4; ++kc) {
                const int j0 = 2 * kc, j1 = 2 * kc + 1;
                float e00 = ex2(s[j0][0] - m0n), e01 = ex2(s[j0][1] - m0n);
                float e02 = ex2(s[j0][2] - m1n), e03 = ex2(s[j0][3] - m1n);
                float e10 = ex2(s[j1][0] - m0n), e11 = ex2(s[j1][1] - m0n);
                float e12 = ex2(s[j1][2] - m1n), e13 = ex2(s[j1][3] - m1n);
                l0 += e00 + e01 + e10 + e11;
                l1 += e02 + e03 + e12 + e13;
                uint32_t a0 = f2h2(e00, e01);
                uint32_t a1 = f2h2(e02, e03);
                uint32_t a2 = f2h2(e10, e11);
                uint32_t a3 = f2h2(e12, e13);
                const int mrow = rbase + kc * 16 + v_row;
                #pragma unroll
                for (int nfp = 0; nfp < 4; ++nfp) {
                    const int nf = 2 * nfp;
                    uint32_t addr = vbase + (uint32_t)(mrow * 128
                                     + (((nf + cv) ^ kv_key) << 4));
                    uint32_t r0, r1, r2, r3;
                    asm volatile("ldmatrix.sync.aligned.m8n8.x4.trans.shared.b16 {%0,%1,%2,%3}, [%4];"
                        : "=r"(r0), "=r"(r1), "=r"(r2), "=r"(r3) : "r"(addr));
                    MMA_F16(o[nf],     a0, a1, a2, a3, r0, r1);
                    MMA_F16(o[nf + 1], a0, a1, a2, a3, r2, r3);
                }
            }
        }
    }

    l0 += __shfl_xor_sync(0xffffffffu, l0, 1);
    l0 += __shfl_xor_sync(0xffffffffu, l0, 2);
    l1 += __shfl_xor_sync(0xffffffffu, l1, 1);
    l1 += __shfl_xor_sync(0xffffffffu, l1, 2);

    float inv0 = 1.0f / l0, inv1 = 1.0f / l1;
    size_t r0g = ((size_t)(h * BB + b) * SS + q0 + wrow + g) * 64;
    size_t r1g = r0g + 8 * 64;
    #pragma unroll
    for (int nf = 0; nf < 8; ++nf) {
        int col = nf * 8 + qr * 2;
        float v0 = o[nf][0] * inv0, v1 = o[nf][1] * inv0;
        float v2 = o[nf][2] * inv1, v3 = o[nf][3] * inv1;
        __nv_bfloat16 h0 = __float2bfloat16_rn(v0), h1 = __float2bfloat16_rn(v1);
        __nv_bfloat16 h2 = __float2bfloat16_rn(v2), h3 = __float2bfloat16_rn(v3);
        __nv_bfloat162 H0; H0.x = h0; H0.y = h1;
        __nv_bfloat162 H1; H1.x = h2; H1.y = h3;
        __nv_bfloat162 L0, L1;
        L0.x = __float2bfloat16_rn(v0 - __bfloat162float(h0));
        L0.y = __float2bfloat16_rn(v1 - __bfloat162float(h1));
        L1.x = __float2bfloat16_rn(v2 - __bfloat162float(h2));
        L1.y = __float2bfloat16_rn(v3 - __bfloat162float(h3));
        *(__nv_bfloat162*)&Xhi[r0g + col] = H0;
        *(__nv_bfloat162*)&Xhi[r1g + col] = H1;
        *(__nv_bfloat162*)&Xlo[r0g + col] = L0;
        *(__nv_bfloat162*)&Xlo[r1g + col] = L1;
    }
}

extern "C" void kernel_launch(void* const* d_in, const int* in_sizes, int n_in,
                              void* d_out, int out_size)
{
    const float* q  = (const float*)d_in[0];
    const float* k  = (const float*)d_in[1];
    const float* v  = (const float*)d_in[2];
    const float* wq = (const float*)d_in[3];
    const float* bq = (const float*)d_in[4];
    const float* wk = (const float*)d_in[5];
    const float* bk = (const float*)d_in[6];
    const float* wv = (const float*)d_in[7];
    const float* bv = (const float*)d_in[8];
    const float* wo = (const float*)d_in[9];
    const float* bo = (const float*)d_in[10];
    float* out = (float*)d_out;

    __nv_bfloat16 *Whi, *Wlo, *Ahi, *Alo, *Qhi, *Qlo, *Khi, *Klo, *Xhi, *Xlo;
    __half *Vh;
    cudaGetSymbolAddress((void**)&Whi, g_Whi);
    cudaGetSymbolAddress((void**)&Wlo, g_Wlo);
    cudaGetSymbolAddress((void**)&Ahi, g_Ahi);
    cudaGetSymbolAddress((void**)&Alo, g_Alo);
    cudaGetSymbolAddress((void**)&Qhi, g_Qhi);
    cudaGetSymbolAddress((void**)&Qlo, g_Qlo);
    cudaGetSymbolAddress((void**)&Khi, g_Khi);
    cudaGetSymbolAddress((void**)&Klo, g_Klo);
    cudaGetSymbolAddress((void**)&Xhi, g_Xhi);
    cudaGetSymbolAddress((void**)&Xlo, g_Xlo);
    cudaGetSymbolAddress((void**)&Vh,  g_Vh);

    cudaFuncSetAttribute(qkv_gemm,    cudaFuncAttributeMaxDynamicSharedMemorySize, GEMM_SMEM);
    cudaFuncSetAttribute(out_gemm,    cudaFuncAttributeMaxDynamicSharedMemorySize, GEMM_SMEM);
    cudaFuncSetAttribute(attn_kernel, cudaFuncAttributeMaxDynamicSharedMemorySize, ATTN_SMEM);

    dim3 tGrid(DD / 32, DD / 32, 4), tBlk(32, 8);
    trans_split_kernel<<<tGrid, tBlk>>>(wq, wk, wv, wo, Whi, Wlo);

    const int n4 = MTOT * DD / 4;
    dim3 sGrid((n4 + 255) / 256, 1, 3);
    split_kernel<<<sGrid, 256>>>(q, k, v, Ahi, Alo, n4);

    dim3 qkvGrid(24, MTOT / 128);
    qkv_gemm<<<qkvGrid, 256, GEMM_SMEM>>>(Ahi, Alo, Whi, Wlo, bq, bk, bv,
                                          Qhi, Qlo, Khi, Klo, Vh);

    dim3 aGrid(SS / 128, BB * HH);
    attn_kernel<<<aGrid, 256, ATTN_SMEM>>>(Qhi, Qlo, Khi, Klo, Vh, Xhi, Xlo);

    dim3 oGrid(DD / 128, MTOT / 128);
    out_gemm<<<oGrid, 256, GEMM_SMEM>>>(Xhi, Xlo, Whi + 3*(size_t)DD*DD, Wlo + 3*(size_t)DD*DD,
                                        bo, out);
}